// round 1
// baseline (speedup 1.0000x reference)
#include <cuda_runtime.h>
#include <math.h>

#define BB 4
#define LQ 2048
#define LK 2048
#define DD 512
#define HH 8
#define DH 64
#define MROWS (BB * LQ)   // 8192

// ---------------- scratch (static device globals; no allocation) -------------
__device__ float g_Qp[BB * LQ * DD];
__device__ float g_Kp[BB * LK * DD];
__device__ float g_Vp[BB * LK * DD];
__device__ float g_attn[BB * LQ * DD];
__device__ float g_x1[BB * LQ * DD];
__device__ float g_y[BB * LQ * DD];

// ---------------- SGEMM: C[M,N] = A[M,K] @ W[K,N] + bias[N] -----------------
// 128x128 tile, BK=8, 256 threads, 8x8 per thread (strided lane mapping).
__global__ __launch_bounds__(256) void sgemm_bias(
    const float* __restrict__ A, const float* __restrict__ W,
    const float* __restrict__ bias, float* __restrict__ C,
    int M, int K, int N)
{
    __shared__ float As[8][128];
    __shared__ float Bs[8][128];
    const int tid = threadIdx.x;
    const int tx = tid & 15, ty = tid >> 4;
    const int row0 = blockIdx.y * 128, col0 = blockIdx.x * 128;

    float acc[8][8];
#pragma unroll
    for (int i = 0; i < 8; i++)
#pragma unroll
        for (int j = 0; j < 8; j++) acc[i][j] = 0.f;

    for (int k0 = 0; k0 < K; k0 += 8) {
        // A tile: 128 rows x 8 cols
        {
            int r = tid >> 1, c4 = (tid & 1) * 4;
            float4 v = *(const float4*)(A + (size_t)(row0 + r) * K + k0 + c4);
            As[c4 + 0][r] = v.x; As[c4 + 1][r] = v.y;
            As[c4 + 2][r] = v.z; As[c4 + 3][r] = v.w;
        }
        // W tile: 8 rows x 128 cols
        {
            int kr = tid >> 5, c4 = (tid & 31) * 4;
            float4 v = *(const float4*)(W + (size_t)(k0 + kr) * N + col0 + c4);
            *(float4*)&Bs[kr][c4] = v;
        }
        __syncthreads();
#pragma unroll
        for (int k = 0; k < 8; k++) {
            float a[8], b[8];
#pragma unroll
            for (int i = 0; i < 8; i++) a[i] = As[k][ty + 16 * i];
#pragma unroll
            for (int j = 0; j < 8; j++) b[j] = Bs[k][tx + 16 * j];
#pragma unroll
            for (int i = 0; i < 8; i++)
#pragma unroll
                for (int j = 0; j < 8; j++)
                    acc[i][j] = fmaf(a[i], b[j], acc[i][j]);
        }
        __syncthreads();
    }
#pragma unroll
    for (int i = 0; i < 8; i++) {
        int r = row0 + ty + 16 * i;
#pragma unroll
        for (int j = 0; j < 8; j++) {
            int c = col0 + tx + 16 * j;
            C[(size_t)r * N + c] = acc[i][j] + bias[c];
        }
    }
}

// ---------------- flash attention (per batch,head) ---------------------------
// BQ=BK=64, Dh=64. 256 threads, each owns 4x4 of S / 4x4 of O via strided
// lane mapping (rows ty+16i, cols tx+16j) -> conflict-free smem access.
// Ks buffer (stride 65) is reused to hold P after the softmax.
#define Bb_Q 64
#define Sstr 65

__global__ __launch_bounds__(256) void flash_attn(
    const float* __restrict__ Qp, const float* __restrict__ Kp,
    const float* __restrict__ Vp, const int* __restrict__ pad,
    float* __restrict__ Out)
{
    extern __shared__ float sm[];
    float* Qs  = sm;                 // 64 * 65
    float* Ks  = Qs + 64 * Sstr;     // 64 * 65 (reused as P)
    float* Vs  = Ks + 64 * Sstr;     // 64 * 64
    float* msk = Vs + 64 * 64;       // 64

    const int tid = threadIdx.x;
    const int tx = tid & 15, ty = tid >> 4;
    const int q0 = blockIdx.x * Bb_Q;
    const int h  = blockIdx.y;
    const int b  = blockIdx.z;
    const size_t baseQ = (size_t)b * LQ * DD + h * DH;
    const size_t baseK = (size_t)b * LK * DD + h * DH;

    // load Q tile (scalar smem stores: stride 65 breaks float4 alignment)
#pragma unroll
    for (int it = 0; it < 4; it++) {
        int f = tid + 256 * it;            // float4 index, 0..1023
        int r = f >> 4, c4 = (f & 15) * 4;
        float4 v = *(const float4*)(Qp + baseQ + (size_t)(q0 + r) * DD + c4);
        float* q = Qs + r * Sstr + c4;
        q[0] = v.x; q[1] = v.y; q[2] = v.z; q[3] = v.w;
    }

    float m_i[4], l_i[4], acc[4][4];
#pragma unroll
    for (int i = 0; i < 4; i++) {
        m_i[i] = -1e30f; l_i[i] = 0.f;
#pragma unroll
        for (int j = 0; j < 4; j++) acc[i][j] = 0.f;
    }
    const float scale = 0.04419417382415922f;   // 1/sqrt(512)

    for (int kt = 0; kt < LK / 64; kt++) {
        __syncthreads();                         // prev O-phase done
        const int k0 = kt * 64;
#pragma unroll
        for (int it = 0; it < 4; it++) {
            int f = tid + 256 * it;
            int r = f >> 4, c4 = (f & 15) * 4;
            float4 v = *(const float4*)(Kp + baseK + (size_t)(k0 + r) * DD + c4);
            float* ks = Ks + r * Sstr + c4;
            ks[0] = v.x; ks[1] = v.y; ks[2] = v.z; ks[3] = v.w;
            float4 w = *(const float4*)(Vp + baseK + (size_t)(k0 + r) * DD + c4);
            *(float4*)(Vs + r * 64 + c4) = w;
        }
        if (tid < 64) msk[tid] = (float)pad[b * LK + k0 + tid];
        __syncthreads();

        // S = Q K^T  (4x4 per thread)
        float s[4][4];
#pragma unroll
        for (int i = 0; i < 4; i++)
#pragma unroll
            for (int j = 0; j < 4; j++) s[i][j] = 0.f;
#pragma unroll 4
        for (int d = 0; d < 64; d++) {
            float q[4], k[4];
#pragma unroll
            for (int i = 0; i < 4; i++) q[i] = Qs[(ty + 16 * i) * Sstr + d];
#pragma unroll
            for (int j = 0; j < 4; j++) k[j] = Ks[(tx + 16 * j) * Sstr + d];
#pragma unroll
            for (int i = 0; i < 4; i++)
#pragma unroll
                for (int j = 0; j < 4; j++)
                    s[i][j] = fmaf(q[i], k[j], s[i][j]);
        }
        // scale + mask (masked -> -1e30: exp underflows to exactly 0,
        // matching the reference's -1e12 fill + post-softmax *mask)
        float mk[4];
#pragma unroll
        for (int j = 0; j < 4; j++) mk[j] = msk[tx + 16 * j];
#pragma unroll
        for (int i = 0; i < 4; i++)
#pragma unroll
            for (int j = 0; j < 4; j++)
                s[i][j] = (mk[j] != 0.f) ? s[i][j] * scale : -1e30f;

        // online softmax per row (rows distributed over 16 tx lanes)
#pragma unroll
        for (int i = 0; i < 4; i++) {
            float mx = fmaxf(fmaxf(s[i][0], s[i][1]), fmaxf(s[i][2], s[i][3]));
#pragma unroll
            for (int o = 8; o > 0; o >>= 1)
                mx = fmaxf(mx, __shfl_xor_sync(0xffffffffu, mx, o));
            float mnew  = fmaxf(m_i[i], mx);
            float alpha = __expf(m_i[i] - mnew);
            float rs = 0.f;
#pragma unroll
            for (int j = 0; j < 4; j++) {
                s[i][j] = __expf(s[i][j] - mnew);
                rs += s[i][j];
            }
#pragma unroll
            for (int o = 8; o > 0; o >>= 1)
                rs += __shfl_xor_sync(0xffffffffu, rs, o);
            l_i[i] = l_i[i] * alpha + rs;
            m_i[i] = mnew;
#pragma unroll
            for (int j = 0; j < 4; j++) acc[i][j] *= alpha;
        }

        __syncthreads();                         // all S reads of Ks done
#pragma unroll
        for (int i = 0; i < 4; i++)
#pragma unroll
            for (int j = 0; j < 4; j++)
                Ks[(ty + 16 * i) * Sstr + (tx + 16 * j)] = s[i][j];
        __syncthreads();

        // O += P @ V
#pragma unroll 4
        for (int j = 0; j < 64; j++) {
            float p[4], v[4];
#pragma unroll
            for (int i = 0; i < 4; i++) p[i] = Ks[(ty + 16 * i) * Sstr + j];
#pragma unroll
            for (int mmi = 0; mmi < 4; mmi++) v[mmi] = Vs[j * 64 + tx + 16 * mmi];
#pragma unroll
            for (int i = 0; i < 4; i++)
#pragma unroll
                for (int mmi = 0; mmi < 4; mmi++)
                    acc[i][mmi] = fmaf(p[i], v[mmi], acc[i][mmi]);
        }
    }

#pragma unroll
    for (int i = 0; i < 4; i++) {
        float inv = 1.f / l_i[i];
        size_t rbase = baseQ + (size_t)(q0 + ty + 16 * i) * DD;
#pragma unroll
        for (int mmi = 0; mmi < 4; mmi++)
            Out[rbase + tx + 16 * mmi] = acc[i][mmi] * inv;
    }
}

// ---------------- residual + layernorm (1 block / row, 128 threads) ----------
// relu_mode=0: t = X + Y;  relu_mode=1: t = X + relu(Y)
__global__ __launch_bounds__(128) void add_ln(
    const float* __restrict__ X, const float* __restrict__ Y,
    const float* __restrict__ g, const float* __restrict__ beta,
    float* __restrict__ out, int relu_mode)
{
    const int row = blockIdx.x;
    const int tid = threadIdx.x;
    const size_t base = (size_t)row * DD;
    float v[4], s = 0.f, s2 = 0.f;
#pragma unroll
    for (int i = 0; i < 4; i++) {
        int c = tid + 128 * i;
        float a = X[base + c];
        float y = Y[base + c];
        float t = relu_mode ? (a + fmaxf(y, 0.f)) : (a + y);
        v[i] = t; s += t; s2 = fmaf(t, t, s2);
    }
#pragma unroll
    for (int o = 16; o > 0; o >>= 1) {
        s  += __shfl_xor_sync(0xffffffffu, s, o);
        s2 += __shfl_xor_sync(0xffffffffu, s2, o);
    }
    __shared__ float sh[8];
    int w = tid >> 5;
    if ((tid & 31) == 0) { sh[w] = s; sh[4 + w] = s2; }
    __syncthreads();
    if (tid == 0) {
        float S  = sh[0] + sh[1] + sh[2] + sh[3];
        float S2 = sh[4] + sh[5] + sh[6] + sh[7];
        float mean = S * (1.f / DD);
        float var  = S2 * (1.f / DD) - mean * mean;
        sh[0] = mean;
        sh[1] = rsqrtf(var + 1e-5f);
    }
    __syncthreads();
    float mean = sh[0], rstd = sh[1];
#pragma unroll
    for (int i = 0; i < 4; i++) {
        int c = tid + 128 * i;
        out[base + c] = (v[i] - mean) * rstd * g[c] + beta[c];
    }
}

// ---------------- launch ------------------------------------------------------
extern "C" void kernel_launch(void* const* d_in, const int* in_sizes, int n_in,
                              void* d_out, int out_size)
{
    const float* Q   = (const float*)d_in[0];
    const float* K   = (const float*)d_in[1];
    const int*   pad = (const int*)  d_in[2];
    const float* Wq  = (const float*)d_in[3];  const float* bq = (const float*)d_in[4];
    const float* Wk  = (const float*)d_in[5];  const float* bk = (const float*)d_in[6];
    const float* Wv  = (const float*)d_in[7];  const float* bv = (const float*)d_in[8];
    const float* Wo  = (const float*)d_in[9];  const float* bo = (const float*)d_in[10];
    const float* g0  = (const float*)d_in[11]; const float* b0 = (const float*)d_in[12];
    const float* g1  = (const float*)d_in[13]; const float* b1 = (const float*)d_in[14];
    float* out = (float*)d_out;

    float *Qp, *Kp, *Vp, *attn, *x1, *y;
    cudaGetSymbolAddress((void**)&Qp,   g_Qp);
    cudaGetSymbolAddress((void**)&Kp,   g_Kp);
    cudaGetSymbolAddress((void**)&Vp,   g_Vp);
    cudaGetSymbolAddress((void**)&attn, g_attn);
    cudaGetSymbolAddress((void**)&x1,   g_x1);
    cudaGetSymbolAddress((void**)&y,    g_y);

    const int smem_flash = (64 * Sstr * 2 + 64 * 64 + 64) * (int)sizeof(float);
    cudaFuncSetAttribute(flash_attn, cudaFuncAttributeMaxDynamicSharedMemorySize,
                         smem_flash);

    dim3 gemm_grid(DD / 128, MROWS / 128);
    sgemm_bias<<<gemm_grid, 256>>>(Q, Wq, bq, Qp, MROWS, DD, DD);
    sgemm_bias<<<gemm_grid, 256>>>(K, Wk, bk, Kp, MROWS, DD, DD);
    sgemm_bias<<<gemm_grid, 256>>>(K, Wv, bv, Vp, MROWS, DD, DD);

    dim3 fgrid(LQ / 64, HH, BB);
    flash_attn<<<fgrid, 256, smem_flash>>>(Qp, Kp, Vp, pad, attn);

    add_ln<<<MROWS, 128>>>(Q, attn, g0, b0, x1, 0);

    sgemm_bias<<<gemm_grid, 256>>>(x1, Wo, bo, y, MROWS, DD, DD);

    add_ln<<<MROWS, 128>>>(x1, y, g1, b1, out, 1);
}

// round 4
// speedup vs baseline: 3.2559x; 3.2559x over previous
#include <cuda_runtime.h>
#include <cuda_bf16.h>
#include <cstdint>
#include <math.h>

#define BB 4
#define LQ 2048
#define LK 2048
#define DD 512
#define HH 8
#define DH 64
#define MROWS (BB * LQ)            // 8192
#define BHN  (BB * HH)             // 32

// ===================== scratch (static device globals) ======================
__device__ __nv_bfloat16 g_Qb [(size_t)MROWS * DD];
__device__ __nv_bfloat16 g_Kb [(size_t)MROWS * DD];
__device__ __nv_bfloat16 g_Qh [(size_t)MROWS * DD];
__device__ __nv_bfloat16 g_Kh [(size_t)MROWS * DD];
__device__ __nv_bfloat16 g_Vh [(size_t)MROWS * DD];
__device__ __nv_bfloat16 g_Vt [(size_t)BHN * DH * LK];
__device__ __nv_bfloat16 g_S  [(size_t)BHN * LQ * LK];     // 256 MB, reused as P
__device__ float         g_attn[(size_t)MROWS * DD];
__device__ float         g_x1 [(size_t)MROWS * DD];
__device__ __nv_bfloat16 g_x1h[(size_t)MROWS * DD];
__device__ __nv_bfloat16 g_x1l[(size_t)MROWS * DD];
__device__ float         g_y  [(size_t)MROWS * DD];
__device__ __nv_bfloat16 g_Wqt[(size_t)DD * DD];
__device__ __nv_bfloat16 g_Wkt[(size_t)DD * DD];
__device__ __nv_bfloat16 g_Wvt[(size_t)DD * DD];
__device__ __nv_bfloat16 g_Woth[(size_t)DD * DD];
__device__ __nv_bfloat16 g_Wotl[(size_t)DD * DD];

// ===================== low-level helpers (sm_80+ only) ======================
__device__ __forceinline__ uint32_t smem_u32(const void* p) {
    uint32_t a;
    asm("{ .reg .u64 t; cvta.to.shared.u64 t, %1; cvt.u32.u64 %0, t; }"
        : "=r"(a) : "l"(p));
    return a;
}
__device__ __forceinline__ void cp_async16(uint32_t dst, const void* src) {
    asm volatile("cp.async.cg.shared.global [%0], [%1], 16;"
                 :: "r"(dst), "l"(src) : "memory");
}
#define CP_COMMIT() asm volatile("cp.async.commit_group;" ::: "memory")

__device__ __forceinline__ void ldm_x4(uint32_t* r, uint32_t addr) {
    asm volatile("ldmatrix.sync.aligned.m8n8.x4.shared.b16 {%0,%1,%2,%3}, [%4];"
                 : "=r"(r[0]), "=r"(r[1]), "=r"(r[2]), "=r"(r[3]) : "r"(addr));
}
__device__ __forceinline__ void ldm_x2(uint32_t* r, uint32_t addr) {
    asm volatile("ldmatrix.sync.aligned.m8n8.x2.shared.b16 {%0,%1}, [%2];"
                 : "=r"(r[0]), "=r"(r[1]) : "r"(addr));
}
__device__ __forceinline__ void mma_bf16(float* d, const uint32_t* a, const uint32_t* b) {
    asm volatile(
        "mma.sync.aligned.m16n8k16.row.col.f32.bf16.bf16.f32 "
        "{%0,%1,%2,%3}, {%4,%5,%6,%7}, {%8,%9}, {%0,%1,%2,%3};"
        : "+f"(d[0]), "+f"(d[1]), "+f"(d[2]), "+f"(d[3])
        : "r"(a[0]), "r"(a[1]), "r"(a[2]), "r"(a[3]), "r"(b[0]), "r"(b[1]));
}

// ===================== generic batched warp-MMA GEMM ========================
// D[128, BN] = sum_K A[128,K] * B[BN,K]^T  (bf16 in, fp32 accum in regs)
// TERMS==3: A = Ahi+Alo, B = Bhi+Blo; computes hi*hi + hi*lo + lo*hi.
// Batch z -> (b = z>>3, h = z&7); operand offsets b*sXb + h*sXh.
// Epilogue: (d + bias) * outScale, written fp32 or bf16.
template<int BN, int TERMS, bool OUT_BF16, bool HAS_BIAS>
__global__ __launch_bounds__(256)
void mma_gemm(const __nv_bfloat16* __restrict__ A,  const __nv_bfloat16* __restrict__ Alo,
              long long lda, long long sAb, long long sAh,
              const __nv_bfloat16* __restrict__ Bm, const __nv_bfloat16* __restrict__ Blo,
              long long ldb, long long sBb, long long sBh,
              void* __restrict__ Cout, long long ldc, long long sCb, long long sCh,
              const float* __restrict__ bias, float outScale, int Ksz)
{
    constexpr int NTm   = (TERMS == 3) ? 2 : 1;
    constexpr int LDS   = 40;                  // padded row (elements): 80B stride
    constexpr int A_ELE = 128 * LDS;
    constexpr int B_ELE = BN * LDS;
    constexpr int STAGE = NTm * (A_ELE + B_ELE);
    constexpr int WN    = BN / 4;              // cols per warp
    constexpr int NT_   = WN / 8;              // n8-tiles per warp

    extern __shared__ __align__(16) __nv_bfloat16 sm_[];
    const int tid = threadIdx.x, wid = tid >> 5, lane = tid & 31;
    const int warp_m = wid & 1, warp_n = wid >> 1;
    const int z = blockIdx.z, bz = z >> 3, hz = z & 7;
    const int m0 = blockIdx.y * 128, n0b = blockIdx.x * BN;

    const __nv_bfloat16* Ab  = A  + bz * sAb + hz * sAh + (long long)m0  * lda;
    const __nv_bfloat16* Bb  = Bm + bz * sBb + hz * sBh + (long long)n0b * ldb;
    const __nv_bfloat16* Abl = (TERMS == 3) ? (Alo + bz * sAb + hz * sAh + (long long)m0  * lda) : nullptr;
    const __nv_bfloat16* Bbl = (TERMS == 3) ? (Blo + bz * sBb + hz * sBh + (long long)n0b * ldb) : nullptr;

    const uint32_t sbase = smem_u32(sm_);

    float acc[4][NT_][4];
#pragma unroll
    for (int i = 0; i < 4; i++)
#pragma unroll
        for (int j = 0; j < NT_; j++)
#pragma unroll
            for (int k = 0; k < 4; k++) acc[i][j][k] = 0.f;

    auto load_stage = [&](int kt, int s) {
        const int koff = kt * 32;
        const uint32_t stA = sbase + (uint32_t)(s * STAGE) * 2;
        const uint32_t stB = stA + (uint32_t)(NTm * A_ELE) * 2;
#pragma unroll
        for (int i = tid; i < 512; i += 256) {          // A hi: 128 rows x 4 chunks
            int r = i >> 2, c = i & 3;
            cp_async16(stA + (uint32_t)(r * LDS + c * 8) * 2,
                       Ab + (long long)r * lda + koff + c * 8);
        }
        if (TERMS == 3) {
#pragma unroll
            for (int i = tid; i < 512; i += 256) {
                int r = i >> 2, c = i & 3;
                cp_async16(stA + (uint32_t)(A_ELE + r * LDS + c * 8) * 2,
                           Abl + (long long)r * lda + koff + c * 8);
            }
        }
#pragma unroll
        for (int i = tid; i < BN * 4; i += 256) {       // B hi
            int r = i >> 2, c = i & 3;
            cp_async16(stB + (uint32_t)(r * LDS + c * 8) * 2,
                       Bb + (long long)r * ldb + koff + c * 8);
        }
        if (TERMS == 3) {
#pragma unroll
            for (int i = tid; i < BN * 4; i += 256) {
                int r = i >> 2, c = i & 3;
                cp_async16(stB + (uint32_t)(B_ELE + r * LDS + c * 8) * 2,
                           Bbl + (long long)r * ldb + koff + c * 8);
            }
        }
        CP_COMMIT();
    };

    auto compute_stage = [&](int s) {
        const uint32_t aBase0 = sbase + (uint32_t)(s * STAGE) * 2;
        const uint32_t bBase0 = aBase0 + (uint32_t)(NTm * A_ELE) * 2;
#pragma unroll
        for (int t = 0; t < TERMS; t++) {
            const uint32_t aB = aBase0 + ((t == 2) ? (uint32_t)A_ELE * 2 : 0u);
            const uint32_t bB = bBase0 + ((t == 1) ? (uint32_t)B_ELE * 2 : 0u);
#pragma unroll
            for (int ks = 0; ks < 2; ks++) {
                uint32_t af[4][4], bf[NT_][2];
#pragma unroll
                for (int mt = 0; mt < 4; mt++) {
                    uint32_t addr = aB + (uint32_t)(
                        (warp_m * 64 + mt * 16 + (lane & 15)) * LDS
                        + ks * 16 + ((lane >> 4) << 3)) * 2;
                    ldm_x4(af[mt], addr);
                }
#pragma unroll
                for (int nt = 0; nt < NT_; nt++) {
                    uint32_t addr = bB + (uint32_t)(
                        (warp_n * WN + nt * 8 + (lane & 7)) * LDS
                        + ks * 16 + (((lane >> 3) & 1) << 3)) * 2;
                    ldm_x2(bf[nt], addr);
                }
#pragma unroll
                for (int mt = 0; mt < 4; mt++)
#pragma unroll
                    for (int nt = 0; nt < NT_; nt++)
                        mma_bf16(acc[mt][nt], af[mt], bf[nt]);
            }
        }
    };

    const int KT = Ksz >> 5;
    load_stage(0, 0);
    for (int kt = 0; kt < KT; kt++) {
        if (kt + 1 < KT) {
            load_stage(kt + 1, (kt + 1) & 1);
            asm volatile("cp.async.wait_group 1;" ::: "memory");
        } else {
            asm volatile("cp.async.wait_group 0;" ::: "memory");
        }
        __syncthreads();
        compute_stage(kt & 1);
        __syncthreads();
    }

    // epilogue
    const long long cOff = bz * sCb + hz * sCh;
#pragma unroll
    for (int mt = 0; mt < 4; mt++) {
        const int rb = m0 + warp_m * 64 + mt * 16 + (lane >> 2);
#pragma unroll
        for (int nt = 0; nt < NT_; nt++) {
            const int c0 = n0b + warp_n * WN + nt * 8 + (lane & 3) * 2;
            float bx = 0.f, by = 0.f;
            if (HAS_BIAS) { bx = bias[c0]; by = bias[c0 + 1]; }
#pragma unroll
            for (int half = 0; half < 2; half++) {
                const int r = rb + half * 8;
                float x0 = (acc[mt][nt][half * 2 + 0] + bx) * outScale;
                float x1 = (acc[mt][nt][half * 2 + 1] + by) * outScale;
                if (OUT_BF16) {
                    __nv_bfloat16* C = (__nv_bfloat16*)Cout + cOff + (long long)r * ldc + c0;
                    *(__nv_bfloat162*)C = __floats2bfloat162_rn(x0, x1);
                } else {
                    float* C = (float*)Cout + cOff + (long long)r * ldc + c0;
                    float2 v; v.x = x0; v.y = x1;
                    *(float2*)C = v;
                }
            }
        }
    }
}

// ===================== small helper kernels =================================
__global__ __launch_bounds__(256) void cvt_bf16(const float* __restrict__ x,
                                                __nv_bfloat16* __restrict__ y)
{
    size_t i = ((size_t)blockIdx.x * 256 + threadIdx.x) * 8;
    float4 a = *(const float4*)(x + i), b = *(const float4*)(x + i + 4);
    __nv_bfloat162 r0 = __floats2bfloat162_rn(a.x, a.y);
    __nv_bfloat162 r1 = __floats2bfloat162_rn(a.z, a.w);
    __nv_bfloat162 r2 = __floats2bfloat162_rn(b.x, b.y);
    __nv_bfloat162 r3 = __floats2bfloat162_rn(b.z, b.w);
    uint4 o;
    o.x = *(uint32_t*)&r0; o.y = *(uint32_t*)&r1;
    o.z = *(uint32_t*)&r2; o.w = *(uint32_t*)&r3;
    *(uint4*)(y + i) = o;
}

__global__ __launch_bounds__(256) void cvt_hilo(const float* __restrict__ x,
                                                __nv_bfloat16* __restrict__ hi,
                                                __nv_bfloat16* __restrict__ lo)
{
    size_t i = ((size_t)blockIdx.x * 256 + threadIdx.x) * 4;
    float4 a = *(const float4*)(x + i);
    float v[4] = {a.x, a.y, a.z, a.w};
    __nv_bfloat16 h[4], l[4];
#pragma unroll
    for (int j = 0; j < 4; j++) {
        h[j] = __float2bfloat16(v[j]);
        l[j] = __float2bfloat16(v[j] - __bfloat162float(h[j]));
    }
    __nv_bfloat162 h0 = {h[0], h[1]}, h1 = {h[2], h[3]};
    __nv_bfloat162 l0 = {l[0], l[1]}, l1 = {l[2], l[3]};
    uint2 ho = {*(uint32_t*)&h0, *(uint32_t*)&h1};
    uint2 loo = {*(uint32_t*)&l0, *(uint32_t*)&l1};
    *(uint2*)(hi + i) = ho;
    *(uint2*)(lo + i) = loo;
}

// W[K,N] fp32 -> Th[N,K] bf16 (+ optional Tl residual)
__global__ void transpose_w(const float* __restrict__ W,
                            __nv_bfloat16* __restrict__ Th,
                            __nv_bfloat16* __restrict__ Tl)
{
    __shared__ float t[32][33];
    const int x = blockIdx.x * 32, y = blockIdx.y * 32;
    const int tx = threadIdx.x, ty = threadIdx.y;
    for (int i = ty; i < 32; i += 8)
        t[i][tx] = W[(size_t)(y + i) * DD + x + tx];
    __syncthreads();
    for (int i = ty; i < 32; i += 8) {
        float v = t[tx][i];
        __nv_bfloat16 hb = __float2bfloat16(v);
        Th[(size_t)(x + i) * DD + y + tx] = hb;
        if (Tl) Tl[(size_t)(x + i) * DD + y + tx] =
            __float2bfloat16(v - __bfloat162float(hb));
    }
}

// Vh[b*2048+t][h*64+dh] bf16 -> Vt[(b*8+h)*64+dh][t] bf16
__global__ void transpose_vh(const __nv_bfloat16* __restrict__ Vh,
                             __nv_bfloat16* __restrict__ Vt)
{
    __shared__ __nv_bfloat16 t[32][33];
    const int z = blockIdx.z, b = z >> 3, h = z & 7;
    const int t0 = blockIdx.x * 32, d0 = blockIdx.y * 32;
    const int tx = threadIdx.x, ty = threadIdx.y;
    for (int i = ty; i < 32; i += 8)
        t[i][tx] = Vh[(size_t)(b * LK + t0 + i) * DD + h * DH + d0 + tx];
    __syncthreads();
    for (int i = ty; i < 32; i += 8)
        Vt[((size_t)z * DH + d0 + i) * LK + t0 + tx] = t[tx][i];
}

// in-place masked softmax over rows of S (bf16), one block per (q, bh) row
__global__ __launch_bounds__(256) void softmax_mask(__nv_bfloat16* __restrict__ S,
                                                    const int* __restrict__ pad)
{
    const int q = blockIdx.x, z = blockIdx.y, b = z >> 3;
    const size_t base = ((size_t)z * LQ + q) * LK;
    const int tid = threadIdx.x;

    uint4 raw = *(const uint4*)(S + base + tid * 8);
    const int4* pm = (const int4*)(pad + b * LK + tid * 8);
    int4 mA = pm[0], mB = pm[1];
    int  mk[8] = {mA.x, mA.y, mA.z, mA.w, mB.x, mB.y, mB.z, mB.w};
    __nv_bfloat162* pr = (__nv_bfloat162*)&raw;
    float v[8];
#pragma unroll
    for (int j = 0; j < 4; j++) {
        float2 f = __bfloat1622float2(pr[j]);
        v[2 * j] = f.x; v[2 * j + 1] = f.y;
    }
    float mx = -1e30f;
#pragma unroll
    for (int j = 0; j < 8; j++) if (mk[j]) mx = fmaxf(mx, v[j]);
#pragma unroll
    for (int o = 16; o > 0; o >>= 1) mx = fmaxf(mx, __shfl_xor_sync(~0u, mx, o));
    __shared__ float sh[8];
    const int w = tid >> 5;
    if ((tid & 31) == 0) sh[w] = mx;
    __syncthreads();
    if (tid < 8) {
        float m2 = sh[tid];
#pragma unroll
        for (int o = 4; o > 0; o >>= 1) m2 = fmaxf(m2, __shfl_xor_sync(0xffu, m2, o));
        if (tid == 0) sh[0] = m2;
    }
    __syncthreads();
    mx = sh[0];

    float p[8], s = 0.f;
#pragma unroll
    for (int j = 0; j < 8; j++) {
        p[j] = mk[j] ? __expf(v[j] - mx) : 0.f;
        s += p[j];
    }
#pragma unroll
    for (int o = 16; o > 0; o >>= 1) s += __shfl_xor_sync(~0u, s, o);
    __syncthreads();
    if ((tid & 31) == 0) sh[w] = s;
    __syncthreads();
    if (tid < 8) {
        float s2 = sh[tid];
#pragma unroll
        for (int o = 4; o > 0; o >>= 1) s2 += __shfl_xor_sync(0xffu, s2, o);
        if (tid == 0) sh[0] = s2;
    }
    __syncthreads();
    const float inv = 1.f / sh[0];

    __nv_bfloat162 o0 = __floats2bfloat162_rn(p[0] * inv, p[1] * inv);
    __nv_bfloat162 o1 = __floats2bfloat162_rn(p[2] * inv, p[3] * inv);
    __nv_bfloat162 o2 = __floats2bfloat162_rn(p[4] * inv, p[5] * inv);
    __nv_bfloat162 o3 = __floats2bfloat162_rn(p[6] * inv, p[7] * inv);
    uint4 ov;
    ov.x = *(uint32_t*)&o0; ov.y = *(uint32_t*)&o1;
    ov.z = *(uint32_t*)&o2; ov.w = *(uint32_t*)&o3;
    *(uint4*)(S + base + tid * 8) = ov;
}

// residual + layernorm. relu_mode=0: t = X+Y; 1: t = X+relu(Y)
__global__ __launch_bounds__(128) void add_ln(
    const float* __restrict__ X, const float* __restrict__ Y,
    const float* __restrict__ g, const float* __restrict__ beta,
    float* __restrict__ out, int relu_mode)
{
    const int row = blockIdx.x;
    const int tid = threadIdx.x;
    const size_t base = (size_t)row * DD;
    float v[4], s = 0.f, s2 = 0.f;
#pragma unroll
    for (int i = 0; i < 4; i++) {
        int c = tid + 128 * i;
        float a = X[base + c];
        float y = Y[base + c];
        float t = relu_mode ? (a + fmaxf(y, 0.f)) : (a + y);
        v[i] = t; s += t; s2 = fmaf(t, t, s2);
    }
#pragma unroll
    for (int o = 16; o > 0; o >>= 1) {
        s  += __shfl_xor_sync(~0u, s, o);
        s2 += __shfl_xor_sync(~0u, s2, o);
    }
    __shared__ float sh[8];
    int w = tid >> 5;
    if ((tid & 31) == 0) { sh[w] = s; sh[4 + w] = s2; }
    __syncthreads();
    if (tid == 0) {
        float S1 = sh[0] + sh[1] + sh[2] + sh[3];
        float S2 = sh[4] + sh[5] + sh[6] + sh[7];
        float mean = S1 * (1.f / DD);
        float var  = S2 * (1.f / DD) - mean * mean;
        sh[0] = mean;
        sh[1] = rsqrtf(var + 1e-5f);
    }
    __syncthreads();
    float mean = sh[0], rstd = sh[1];
#pragma unroll
    for (int i = 0; i < 4; i++) {
        int c = tid + 128 * i;
        out[base + c] = (v[i] - mean) * rstd * g[c] + beta[c];
    }
}

// ===================== launch ===============================================
extern "C" void kernel_launch(void* const* d_in, const int* in_sizes, int n_in,
                              void* d_out, int out_size)
{
    const float* Q   = (const float*)d_in[0];
    const float* K   = (const float*)d_in[1];
    const int*   pad = (const int*)  d_in[2];
    const float* Wq  = (const float*)d_in[3];  const float* bq = (const float*)d_in[4];
    const float* Wk  = (const float*)d_in[5];  const float* bk = (const float*)d_in[6];
    const float* Wv  = (const float*)d_in[7];  const float* bv = (const float*)d_in[8];
    const float* Wo  = (const float*)d_in[9];  const float* bo = (const float*)d_in[10];
    const float* g0  = (const float*)d_in[11]; const float* b0 = (const float*)d_in[12];
    const float* g1  = (const float*)d_in[13]; const float* b1 = (const float*)d_in[14];
    float* out = (float*)d_out;

    __nv_bfloat16 *Qb, *Kb, *Qh, *Kh, *Vh, *Vt, *S, *x1h, *x1l, *Wqt, *Wkt, *Wvt, *Woth, *Wotl;
    float *attn, *x1, *y;
    cudaGetSymbolAddress((void**)&Qb,   g_Qb);   cudaGetSymbolAddress((void**)&Kb,   g_Kb);
    cudaGetSymbolAddress((void**)&Qh,   g_Qh);   cudaGetSymbolAddress((void**)&Kh,   g_Kh);
    cudaGetSymbolAddress((void**)&Vh,   g_Vh);   cudaGetSymbolAddress((void**)&Vt,   g_Vt);
    cudaGetSymbolAddress((void**)&S,    g_S);
    cudaGetSymbolAddress((void**)&attn, g_attn); cudaGetSymbolAddress((void**)&x1,   g_x1);
    cudaGetSymbolAddress((void**)&x1h,  g_x1h);  cudaGetSymbolAddress((void**)&x1l,  g_x1l);
    cudaGetSymbolAddress((void**)&y,    g_y);
    cudaGetSymbolAddress((void**)&Wqt,  g_Wqt);  cudaGetSymbolAddress((void**)&Wkt,  g_Wkt);
    cudaGetSymbolAddress((void**)&Wvt,  g_Wvt);
    cudaGetSymbolAddress((void**)&Woth, g_Woth); cudaGetSymbolAddress((void**)&Wotl, g_Wotl);

    // dynamic smem sizes: 2 stages * NTm*(128+BN)*40 elements * 2 bytes
    const int smem_g1 = 2 * 1 * (128 + 128) * 40 * 2;   // 40960
    const int smem_pv = 2 * 1 * (128 + 64)  * 40 * 2;   // 30720
    const int smem_g3 = 2 * 2 * (128 + 128) * 40 * 2;   // 81920
    cudaFuncSetAttribute((const void*)mma_gemm<128, 1, true,  true >,
                         cudaFuncAttributeMaxDynamicSharedMemorySize, smem_g1);
    cudaFuncSetAttribute((const void*)mma_gemm<128, 1, true,  false>,
                         cudaFuncAttributeMaxDynamicSharedMemorySize, smem_g1);
    cudaFuncSetAttribute((const void*)mma_gemm<64,  1, false, false>,
                         cudaFuncAttributeMaxDynamicSharedMemorySize, smem_pv);
    cudaFuncSetAttribute((const void*)mma_gemm<128, 3, false, true >,
                         cudaFuncAttributeMaxDynamicSharedMemorySize, smem_g3);

    const float invs = 0.04419417382415922f;  // 1/sqrt(512)

    // inputs -> bf16
    cvt_bf16<<<(MROWS * DD) / (256 * 8), 256>>>(Q, Qb);
    cvt_bf16<<<(MROWS * DD) / (256 * 8), 256>>>(K, Kb);
    // weights -> transposed bf16 (Wo split hi/lo)
    dim3 twg(16, 16), twb(32, 8);
    transpose_w<<<twg, twb>>>(Wq, Wqt, nullptr);
    transpose_w<<<twg, twb>>>(Wk, Wkt, nullptr);
    transpose_w<<<twg, twb>>>(Wv, Wvt, nullptr);
    transpose_w<<<twg, twb>>>(Wo, Woth, Wotl);

    // projections: out bf16 (Qh pre-scaled by 1/sqrt(D))
    dim3 pg(DD / 128, MROWS / 128, 1);
    mma_gemm<128, 1, true, true><<<pg, 256, smem_g1>>>(
        Qb, nullptr, DD, 0, 0, Wqt, nullptr, DD, 0, 0, Qh, DD, 0, 0, bq, invs, DD);
    mma_gemm<128, 1, true, true><<<pg, 256, smem_g1>>>(
        Kb, nullptr, DD, 0, 0, Wkt, nullptr, DD, 0, 0, Kh, DD, 0, 0, bk, 1.0f, DD);
    mma_gemm<128, 1, true, true><<<pg, 256, smem_g1>>>(
        Kb, nullptr, DD, 0, 0, Wvt, nullptr, DD, 0, 0, Vh, DD, 0, 0, bv, 1.0f, DD);

    transpose_vh<<<dim3(LK / 32, DH / 32, BHN), twb>>>(Vh, Vt);

    // S = Qh Kh^T, batched over (b,h); out bf16
    dim3 sg(LK / 128, LQ / 128, BHN);
    mma_gemm<128, 1, true, false><<<sg, 256, smem_g1>>>(
        Qh, nullptr, DD, (long long)LQ * DD, DH,
        Kh, nullptr, DD, (long long)LK * DD, DH,
        S, LK, (long long)HH * LQ * LK, (long long)LQ * LK,
        nullptr, 1.0f, DH);

    softmax_mask<<<dim3(LQ, BHN), 256>>>(S, pad);

    // O = P Vt^T  (K = 2048)
    dim3 og(1, LQ / 128, BHN);
    mma_gemm<64, 1, false, false><<<og, 256, smem_pv>>>(
        S, nullptr, LK, (long long)HH * LQ * LK, (long long)LQ * LK,
        Vt, nullptr, LK, (long long)HH * DH * LK, (long long)DH * LK,
        attn, DD, (long long)LQ * DD, DH,
        nullptr, 1.0f, LK);

    add_ln<<<MROWS, 128>>>(Q, attn, g0, b0, x1, 0);

    // Wo GEMM in 3-term bf16 hi/lo split (accuracy-critical path)
    cvt_hilo<<<(MROWS * DD) / (256 * 4), 256>>>(x1, x1h, x1l);
    mma_gemm<128, 3, false, true><<<pg, 256, smem_g3>>>(
        x1h, x1l, DD, 0, 0, Woth, Wotl, DD, 0, 0, y, DD, 0, 0, bo, 1.0f, DD);

    add_ln<<<MROWS, 128>>>(x1, y, g1, b1, out, 1);
}

// round 5
// speedup vs baseline: 4.3055x; 1.3224x over previous
#include <cuda_runtime.h>
#include <cuda_bf16.h>
#include <cstdint>
#include <math.h>

#define BB 4
#define LQ 2048
#define LK 2048
#define DD 512
#define HH 8
#define DH 64
#define MROWS (BB * LQ)            // 8192
#define BHN  (BB * HH)             // 32

// ===================== scratch (static device globals) ======================
__device__ __nv_bfloat16 g_Qb [(size_t)MROWS * DD];
__device__ __nv_bfloat16 g_Kb [(size_t)MROWS * DD];
__device__ __nv_bfloat16 g_Qh [(size_t)MROWS * DD];
__device__ __nv_bfloat16 g_Kh [(size_t)MROWS * DD];
__device__ __nv_bfloat16 g_Vh [(size_t)MROWS * DD];
__device__ float         g_attn[(size_t)MROWS * DD];
__device__ float         g_x1 [(size_t)MROWS * DD];
__device__ __nv_bfloat16 g_x1h[(size_t)MROWS * DD];
__device__ __nv_bfloat16 g_x1l[(size_t)MROWS * DD];
__device__ float         g_y  [(size_t)MROWS * DD];
__device__ __nv_bfloat16 g_Wqt[(size_t)DD * DD];
__device__ __nv_bfloat16 g_Wkt[(size_t)DD * DD];
__device__ __nv_bfloat16 g_Wvt[(size_t)DD * DD];
__device__ __nv_bfloat16 g_Woth[(size_t)DD * DD];
__device__ __nv_bfloat16 g_Wotl[(size_t)DD * DD];

// ===================== low-level helpers (sm_80+ only) ======================
__device__ __forceinline__ uint32_t smem_u32(const void* p) {
    uint32_t a;
    asm("{ .reg .u64 t; cvta.to.shared.u64 t, %1; cvt.u32.u64 %0, t; }"
        : "=r"(a) : "l"(p));
    return a;
}
__device__ __forceinline__ void cp_async16(uint32_t dst, const void* src) {
    asm volatile("cp.async.cg.shared.global [%0], [%1], 16;"
                 :: "r"(dst), "l"(src) : "memory");
}
#define CP_COMMIT() asm volatile("cp.async.commit_group;" ::: "memory")

__device__ __forceinline__ void ldm_x4(uint32_t* r, uint32_t addr) {
    asm volatile("ldmatrix.sync.aligned.m8n8.x4.shared.b16 {%0,%1,%2,%3}, [%4];"
                 : "=r"(r[0]), "=r"(r[1]), "=r"(r[2]), "=r"(r[3]) : "r"(addr));
}
__device__ __forceinline__ void ldm_x4_t(uint32_t* r, uint32_t addr) {
    asm volatile("ldmatrix.sync.aligned.m8n8.x4.trans.shared.b16 {%0,%1,%2,%3}, [%4];"
                 : "=r"(r[0]), "=r"(r[1]), "=r"(r[2]), "=r"(r[3]) : "r"(addr));
}
__device__ __forceinline__ void ldm_x2(uint32_t* r, uint32_t addr) {
    asm volatile("ldmatrix.sync.aligned.m8n8.x2.shared.b16 {%0,%1}, [%2];"
                 : "=r"(r[0]), "=r"(r[1]) : "r"(addr));
}
__device__ __forceinline__ void mma_bf16(float* d, const uint32_t* a, const uint32_t* b) {
    asm volatile(
        "mma.sync.aligned.m16n8k16.row.col.f32.bf16.bf16.f32 "
        "{%0,%1,%2,%3}, {%4,%5,%6,%7}, {%8,%9}, {%0,%1,%2,%3};"
        : "+f"(d[0]), "+f"(d[1]), "+f"(d[2]), "+f"(d[3])
        : "r"(a[0]), "r"(a[1]), "r"(a[2]), "r"(a[3]), "r"(b[0]), "r"(b[1]));
}
__device__ __forceinline__ uint32_t packbf(float a, float b) {
    __nv_bfloat162 t = __floats2bfloat162_rn(a, b);
    return *(uint32_t*)&t;
}

// ===================== generic batched warp-MMA GEMM ========================
// D[128, BN] = sum_K A[128,K] * B[BN,K]^T  (bf16 in, fp32 accum in regs)
// TERMS==3: A = Ahi+Alo, B = Bhi+Blo; computes hi*hi + hi*lo + lo*hi.
template<int BN, int TERMS, bool OUT_BF16, bool HAS_BIAS>
__global__ __launch_bounds__(256)
void mma_gemm(const __nv_bfloat16* __restrict__ A,  const __nv_bfloat16* __restrict__ Alo,
              long long lda,
              const __nv_bfloat16* __restrict__ Bm, const __nv_bfloat16* __restrict__ Blo,
              long long ldb,
              void* __restrict__ Cout, long long ldc,
              const float* __restrict__ bias, float outScale, int Ksz)
{
    constexpr int NTm   = (TERMS == 3) ? 2 : 1;
    constexpr int LDS   = 40;                  // padded row (elements): 80B stride
    constexpr int A_ELE = 128 * LDS;
    constexpr int B_ELE = BN * LDS;
    constexpr int STAGE = NTm * (A_ELE + B_ELE);
    constexpr int WN    = BN / 4;              // cols per warp
    constexpr int NT_   = WN / 8;              // n8-tiles per warp

    extern __shared__ __align__(16) __nv_bfloat16 sm_[];
    const int tid = threadIdx.x, wid = tid >> 5, lane = tid & 31;
    const int warp_m = wid & 1, warp_n = wid >> 1;
    const int m0 = blockIdx.y * 128, n0b = blockIdx.x * BN;

    const __nv_bfloat16* Ab  = A  + (long long)m0  * lda;
    const __nv_bfloat16* Bb  = Bm + (long long)n0b * ldb;
    const __nv_bfloat16* Abl = (TERMS == 3) ? (Alo + (long long)m0  * lda) : nullptr;
    const __nv_bfloat16* Bbl = (TERMS == 3) ? (Blo + (long long)n0b * ldb) : nullptr;

    const uint32_t sbase = smem_u32(sm_);

    float acc[4][NT_][4];
#pragma unroll
    for (int i = 0; i < 4; i++)
#pragma unroll
        for (int j = 0; j < NT_; j++)
#pragma unroll
            for (int k = 0; k < 4; k++) acc[i][j][k] = 0.f;

    auto load_stage = [&](int kt, int s) {
        const int koff = kt * 32;
        const uint32_t stA = sbase + (uint32_t)(s * STAGE) * 2;
        const uint32_t stB = stA + (uint32_t)(NTm * A_ELE) * 2;
#pragma unroll
        for (int i = tid; i < 512; i += 256) {
            int r = i >> 2, c = i & 3;
            cp_async16(stA + (uint32_t)(r * LDS + c * 8) * 2,
                       Ab + (long long)r * lda + koff + c * 8);
        }
        if (TERMS == 3) {
#pragma unroll
            for (int i = tid; i < 512; i += 256) {
                int r = i >> 2, c = i & 3;
                cp_async16(stA + (uint32_t)(A_ELE + r * LDS + c * 8) * 2,
                           Abl + (long long)r * lda + koff + c * 8);
            }
        }
#pragma unroll
        for (int i = tid; i < BN * 4; i += 256) {
            int r = i >> 2, c = i & 3;
            cp_async16(stB + (uint32_t)(r * LDS + c * 8) * 2,
                       Bb + (long long)r * ldb + koff + c * 8);
        }
        if (TERMS == 3) {
#pragma unroll
            for (int i = tid; i < BN * 4; i += 256) {
                int r = i >> 2, c = i & 3;
                cp_async16(stB + (uint32_t)(B_ELE + r * LDS + c * 8) * 2,
                           Bbl + (long long)r * ldb + koff + c * 8);
            }
        }
        CP_COMMIT();
    };

    auto compute_stage = [&](int s) {
        const uint32_t aBase0 = sbase + (uint32_t)(s * STAGE) * 2;
        const uint32_t bBase0 = aBase0 + (uint32_t)(NTm * A_ELE) * 2;
#pragma unroll
        for (int t = 0; t < TERMS; t++) {
            const uint32_t aB = aBase0 + ((t == 2) ? (uint32_t)A_ELE * 2 : 0u);
            const uint32_t bB = bBase0 + ((t == 1) ? (uint32_t)B_ELE * 2 : 0u);
#pragma unroll
            for (int ks = 0; ks < 2; ks++) {
                uint32_t af[4][4], bf[NT_][2];
#pragma unroll
                for (int mt = 0; mt < 4; mt++) {
                    uint32_t addr = aB + (uint32_t)(
                        (warp_m * 64 + mt * 16 + (lane & 15)) * LDS
                        + ks * 16 + ((lane >> 4) << 3)) * 2;
                    ldm_x4(af[mt], addr);
                }
#pragma unroll
                for (int nt = 0; nt < NT_; nt++) {
                    uint32_t addr = bB + (uint32_t)(
                        (warp_n * WN + nt * 8 + (lane & 7)) * LDS
                        + ks * 16 + (((lane >> 3) & 1) << 3)) * 2;
                    ldm_x2(bf[nt], addr);
                }
#pragma unroll
                for (int mt = 0; mt < 4; mt++)
#pragma unroll
                    for (int nt = 0; nt < NT_; nt++)
                        mma_bf16(acc[mt][nt], af[mt], bf[nt]);
            }
        }
    };

    const int KT = Ksz >> 5;
    load_stage(0, 0);
    for (int kt = 0; kt < KT; kt++) {
        if (kt + 1 < KT) {
            load_stage(kt + 1, (kt + 1) & 1);
            asm volatile("cp.async.wait_group 1;" ::: "memory");
        } else {
            asm volatile("cp.async.wait_group 0;" ::: "memory");
        }
        __syncthreads();
        compute_stage(kt & 1);
        __syncthreads();
    }

    // epilogue
#pragma unroll
    for (int mt = 0; mt < 4; mt++) {
        const int rb = m0 + warp_m * 64 + mt * 16 + (lane >> 2);
#pragma unroll
        for (int nt = 0; nt < NT_; nt++) {
            const int c0 = n0b + warp_n * WN + nt * 8 + (lane & 3) * 2;
            float bx = 0.f, by = 0.f;
            if (HAS_BIAS) { bx = bias[c0]; by = bias[c0 + 1]; }
#pragma unroll
            for (int half = 0; half < 2; half++) {
                const int r = rb + half * 8;
                float x0 = (acc[mt][nt][half * 2 + 0] + bx) * outScale;
                float x1 = (acc[mt][nt][half * 2 + 1] + by) * outScale;
                if (OUT_BF16) {
                    __nv_bfloat16* C = (__nv_bfloat16*)Cout + (long long)r * ldc + c0;
                    *(__nv_bfloat162*)C = __floats2bfloat162_rn(x0, x1);
                } else {
                    float* C = (float*)Cout + (long long)r * ldc + c0;
                    float2 v; v.x = x0; v.y = x1;
                    *(float2*)C = v;
                }
            }
        }
    }
}

// ===================== fused flash attention (mma.sync) =====================
// Grid: (LQ/128, BHN). 256 threads = 8 warps; warp w owns rows 16w..16w+15.
// K/V tiles 64 keys, double-buffered cp.async. Online softmax in registers.
#define FBQ 128
#define FBK 64
#define FLDS 72      // padded row: 144 B stride -> ldmatrix conflict-free

__global__ __launch_bounds__(256, 1)
void flash_mma(const __nv_bfloat16* __restrict__ Qh,
               const __nv_bfloat16* __restrict__ Kh,
               const __nv_bfloat16* __restrict__ Vh,
               const int* __restrict__ pad,
               float* __restrict__ Out)
{
    extern __shared__ __align__(16) char fsm[];
    __nv_bfloat16* Qs = (__nv_bfloat16*)fsm;            // 128*72
    __nv_bfloat16* Ks = Qs + FBQ * FLDS;                // 2 * 64*72
    __nv_bfloat16* Vs = Ks + 2 * FBK * FLDS;            // 2 * 64*72
    int*           Ms = (int*)(Vs + 2 * FBK * FLDS);    // 2 * 64

    const int tid = threadIdx.x, wid = tid >> 5, lane = tid & 31;
    const int q0 = blockIdx.x * FBQ;
    const int z = blockIdx.y, b = z >> 3, h = z & 7;
    const uint32_t sQ = smem_u32(Qs), sK = smem_u32(Ks);
    const uint32_t sV = smem_u32(Vs), sM = smem_u32(Ms);

    const __nv_bfloat16* Qp = Qh + ((size_t)(b * LQ + q0)) * DD + h * DH;
    const __nv_bfloat16* Kp = Kh + ((size_t)b * LK) * DD + h * DH;
    const __nv_bfloat16* Vp = Vh + ((size_t)b * LK) * DD + h * DH;
    const int* pp = pad + b * LK;

    // Q tile -> smem
#pragma unroll
    for (int i = tid; i < 1024; i += 256) {
        int r = i >> 3, c = i & 7;
        cp_async16(sQ + (uint32_t)(r * FLDS + c * 8) * 2, Qp + (size_t)r * DD + c * 8);
    }
    CP_COMMIT();

    auto load_kv = [&](int kt, int s) {
        const int k0 = kt * FBK;
        const uint32_t kb = sK + (uint32_t)(s * FBK * FLDS) * 2;
        const uint32_t vb = sV + (uint32_t)(s * FBK * FLDS) * 2;
#pragma unroll
        for (int i = tid; i < 512; i += 256) {
            int r = i >> 3, c = i & 7;
            cp_async16(kb + (uint32_t)(r * FLDS + c * 8) * 2, Kp + (size_t)(k0 + r) * DD + c * 8);
            cp_async16(vb + (uint32_t)(r * FLDS + c * 8) * 2, Vp + (size_t)(k0 + r) * DD + c * 8);
        }
        if (tid < 16)
            cp_async16(sM + (uint32_t)(s * 64 + tid * 4) * 4, pp + k0 + tid * 4);
        CP_COMMIT();
    };

    load_kv(0, 0);

    uint32_t qf[4][4];
    float o[8][4];
#pragma unroll
    for (int i = 0; i < 8; i++)
#pragma unroll
        for (int j = 0; j < 4; j++) o[i][j] = 0.f;
    float m0 = -1e30f, m1 = -1e30f, l0 = 0.f, l1 = 0.f;

    const int NKT = LK / FBK;   // 32
    for (int kt = 0; kt < NKT; kt++) {
        const int s = kt & 1;
        if (kt + 1 < NKT) {
            load_kv(kt + 1, s ^ 1);
            asm volatile("cp.async.wait_group 1;" ::: "memory");
        } else {
            asm volatile("cp.async.wait_group 0;" ::: "memory");
        }
        __syncthreads();
        if (kt == 0) {
#pragma unroll
            for (int ks = 0; ks < 4; ks++) {
                uint32_t addr = sQ + (uint32_t)(
                    (wid * 16 + (lane & 15)) * FLDS + ks * 16 + ((lane >> 4) << 3)) * 2;
                ldm_x4(qf[ks], addr);
            }
        }

        const uint32_t kb = sK + (uint32_t)(s * FBK * FLDS) * 2;
        const uint32_t vb = sV + (uint32_t)(s * FBK * FLDS) * 2;
        const int* mskp = Ms + s * 64;

        // ---- S = Q K^T ----
        float sa[8][4];
#pragma unroll
        for (int i = 0; i < 8; i++)
#pragma unroll
            for (int j = 0; j < 4; j++) sa[i][j] = 0.f;
#pragma unroll
        for (int ks = 0; ks < 4; ks++) {
            uint32_t bk[8][2];
#pragma unroll
            for (int np = 0; np < 4; np++) {
                uint32_t r4[4];
                uint32_t addr = kb + (uint32_t)(
                    (np * 16 + (lane & 15)) * FLDS + ks * 16 + ((lane >> 4) << 3)) * 2;
                ldm_x4(r4, addr);
                bk[2 * np][0] = r4[0]; bk[2 * np][1] = r4[2];
                bk[2 * np + 1][0] = r4[1]; bk[2 * np + 1][1] = r4[3];
            }
#pragma unroll
            for (int nt = 0; nt < 8; nt++) mma_bf16(sa[nt], qf[ks], bk[nt]);
        }

        // ---- masked online softmax ----
        const int cb = (lane & 3) * 2;
        int mk0[8], mk1[8];
#pragma unroll
        for (int nt = 0; nt < 8; nt++) {
            mk0[nt] = mskp[nt * 8 + cb];
            mk1[nt] = mskp[nt * 8 + cb + 1];
        }
        float mx0 = -1e30f, mx1 = -1e30f;
#pragma unroll
        for (int nt = 0; nt < 8; nt++) {
            if (mk0[nt]) { mx0 = fmaxf(mx0, sa[nt][0]); mx1 = fmaxf(mx1, sa[nt][2]); }
            if (mk1[nt]) { mx0 = fmaxf(mx0, sa[nt][1]); mx1 = fmaxf(mx1, sa[nt][3]); }
        }
        mx0 = fmaxf(mx0, __shfl_xor_sync(~0u, mx0, 1));
        mx0 = fmaxf(mx0, __shfl_xor_sync(~0u, mx0, 2));
        mx1 = fmaxf(mx1, __shfl_xor_sync(~0u, mx1, 1));
        mx1 = fmaxf(mx1, __shfl_xor_sync(~0u, mx1, 2));
        const float mn0 = fmaxf(m0, mx0), mn1 = fmaxf(m1, mx1);
        const float al0 = __expf(m0 - mn0), al1 = __expf(m1 - mn1);
        m0 = mn0; m1 = mn1;
        float rs0 = 0.f, rs1 = 0.f;
#pragma unroll
        for (int nt = 0; nt < 8; nt++) {
            sa[nt][0] = mk0[nt] ? __expf(sa[nt][0] - mn0) : 0.f;
            sa[nt][1] = mk1[nt] ? __expf(sa[nt][1] - mn0) : 0.f;
            sa[nt][2] = mk0[nt] ? __expf(sa[nt][2] - mn1) : 0.f;
            sa[nt][3] = mk1[nt] ? __expf(sa[nt][3] - mn1) : 0.f;
            rs0 += sa[nt][0] + sa[nt][1];
            rs1 += sa[nt][2] + sa[nt][3];
        }
        rs0 += __shfl_xor_sync(~0u, rs0, 1); rs0 += __shfl_xor_sync(~0u, rs0, 2);
        rs1 += __shfl_xor_sync(~0u, rs1, 1); rs1 += __shfl_xor_sync(~0u, rs1, 2);
        l0 = l0 * al0 + rs0;
        l1 = l1 * al1 + rs1;
#pragma unroll
        for (int nt = 0; nt < 8; nt++) {
            o[nt][0] *= al0; o[nt][1] *= al0;
            o[nt][2] *= al1; o[nt][3] *= al1;
        }

        // ---- O += P V  (P from accumulator layout, V via ldmatrix.trans) ----
#pragma unroll
        for (int ks = 0; ks < 4; ks++) {
            uint32_t pa[4];
            pa[0] = packbf(sa[2 * ks][0],     sa[2 * ks][1]);
            pa[1] = packbf(sa[2 * ks][2],     sa[2 * ks][3]);
            pa[2] = packbf(sa[2 * ks + 1][0], sa[2 * ks + 1][1]);
            pa[3] = packbf(sa[2 * ks + 1][2], sa[2 * ks + 1][3]);
#pragma unroll
            for (int np = 0; np < 4; np++) {
                uint32_t r4[4];
                uint32_t addr = vb + (uint32_t)(
                    (ks * 16 + (lane & 15)) * FLDS + np * 16 + ((lane >> 4) << 3)) * 2;
                ldm_x4_t(r4, addr);
                mma_bf16(o[2 * np],     pa, r4);
                mma_bf16(o[2 * np + 1], pa, r4 + 2);
            }
        }
        __syncthreads();
    }

    // ---- write O / l ----
    const float inv0 = (l0 > 0.f) ? 1.f / l0 : 0.f;
    const float inv1 = (l1 > 0.f) ? 1.f / l1 : 0.f;
    const int r0g = q0 + wid * 16 + (lane >> 2);
    float* ob0 = Out + ((size_t)(b * LQ + r0g)) * DD + h * DH + (lane & 3) * 2;
    float* ob1 = ob0 + (size_t)8 * DD;
#pragma unroll
    for (int nt = 0; nt < 8; nt++) {
        float2 v0; v0.x = o[nt][0] * inv0; v0.y = o[nt][1] * inv0;
        float2 v1; v1.x = o[nt][2] * inv1; v1.y = o[nt][3] * inv1;
        *(float2*)(ob0 + nt * 8) = v0;
        *(float2*)(ob1 + nt * 8) = v1;
    }
}

// ===================== small helper kernels =================================
__global__ __launch_bounds__(256) void cvt_bf16(const float* __restrict__ x,
                                                __nv_bfloat16* __restrict__ y)
{
    size_t i = ((size_t)blockIdx.x * 256 + threadIdx.x) * 8;
    float4 a = *(const float4*)(x + i), b = *(const float4*)(x + i + 4);
    __nv_bfloat162 r0 = __floats2bfloat162_rn(a.x, a.y);
    __nv_bfloat162 r1 = __floats2bfloat162_rn(a.z, a.w);
    __nv_bfloat162 r2 = __floats2bfloat162_rn(b.x, b.y);
    __nv_bfloat162 r3 = __floats2bfloat162_rn(b.z, b.w);
    uint4 o;
    o.x = *(uint32_t*)&r0; o.y = *(uint32_t*)&r1;
    o.z = *(uint32_t*)&r2; o.w = *(uint32_t*)&r3;
    *(uint4*)(y + i) = o;
}

// W[K,N] fp32 -> Th[N,K] bf16 (+ optional Tl residual)
__global__ void transpose_w(const float* __restrict__ W,
                            __nv_bfloat16* __restrict__ Th,
                            __nv_bfloat16* __restrict__ Tl)
{
    __shared__ float t[32][33];
    const int x = blockIdx.x * 32, y = blockIdx.y * 32;
    const int tx = threadIdx.x, ty = threadIdx.y;
    for (int i = ty; i < 32; i += 8)
        t[i][tx] = W[(size_t)(y + i) * DD + x + tx];
    __syncthreads();
    for (int i = ty; i < 32; i += 8) {
        float v = t[tx][i];
        __nv_bfloat16 hb = __float2bfloat16(v);
        Th[(size_t)(x + i) * DD + y + tx] = hb;
        if (Tl) Tl[(size_t)(x + i) * DD + y + tx] =
            __float2bfloat16(v - __bfloat162float(hb));
    }
}

// residual + layernorm. relu_mode=0: t=X+Y; 1: t=X+relu(Y).
// Optionally also emits hi/lo bf16 split of the result (for the Wo GEMM).
__global__ __launch_bounds__(128) void add_ln(
    const float* __restrict__ X, const float* __restrict__ Y,
    const float* __restrict__ g, const float* __restrict__ beta,
    float* __restrict__ out, __nv_bfloat16* __restrict__ ohi,
    __nv_bfloat16* __restrict__ olo, int relu_mode)
{
    const int row = blockIdx.x;
    const int tid = threadIdx.x;
    const size_t base = (size_t)row * DD;
    float v[4], s = 0.f, s2 = 0.f;
#pragma unroll
    for (int i = 0; i < 4; i++) {
        int c = tid + 128 * i;
        float a = X[base + c];
        float y = Y[base + c];
        float t = relu_mode ? (a + fmaxf(y, 0.f)) : (a + y);
        v[i] = t; s += t; s2 = fmaf(t, t, s2);
    }
#pragma unroll
    for (int o = 16; o > 0; o >>= 1) {
        s  += __shfl_xor_sync(~0u, s, o);
        s2 += __shfl_xor_sync(~0u, s2, o);
    }
    __shared__ float sh[8];
    int w = tid >> 5;
    if ((tid & 31) == 0) { sh[w] = s; sh[4 + w] = s2; }
    __syncthreads();
    if (tid == 0) {
        float S1 = sh[0] + sh[1] + sh[2] + sh[3];
        float S2 = sh[4] + sh[5] + sh[6] + sh[7];
        float mean = S1 * (1.f / DD);
        float var  = S2 * (1.f / DD) - mean * mean;
        sh[0] = mean;
        sh[1] = rsqrtf(var + 1e-5f);
    }
    __syncthreads();
    float mean = sh[0], rstd = sh[1];
#pragma unroll
    for (int i = 0; i < 4; i++) {
        int c = tid + 128 * i;
        float t = (v[i] - mean) * rstd * g[c] + beta[c];
        out[base + c] = t;
        if (ohi) {
            __nv_bfloat16 hb = __float2bfloat16(t);
            ohi[base + c] = hb;
            olo[base + c] = __float2bfloat16(t - __bfloat162float(hb));
        }
    }
}

// ===================== launch ===============================================
extern "C" void kernel_launch(void* const* d_in, const int* in_sizes, int n_in,
                              void* d_out, int out_size)
{
    const float* Q   = (const float*)d_in[0];
    const float* K   = (const float*)d_in[1];
    const int*   pad = (const int*)  d_in[2];
    const float* Wq  = (const float*)d_in[3];  const float* bq = (const float*)d_in[4];
    const float* Wk  = (const float*)d_in[5];  const float* bk = (const float*)d_in[6];
    const float* Wv  = (const float*)d_in[7];  const float* bv = (const float*)d_in[8];
    const float* Wo  = (const float*)d_in[9];  const float* bo = (const float*)d_in[10];
    const float* g0  = (const float*)d_in[11]; const float* b0 = (const float*)d_in[12];
    const float* g1  = (const float*)d_in[13]; const float* b1 = (const float*)d_in[14];
    float* out = (float*)d_out;

    __nv_bfloat16 *Qb, *Kb, *Qh, *Kh, *Vh, *x1h, *x1l, *Wqt, *Wkt, *Wvt, *Woth, *Wotl;
    float *attn, *x1, *y;
    cudaGetSymbolAddress((void**)&Qb,   g_Qb);   cudaGetSymbolAddress((void**)&Kb,   g_Kb);
    cudaGetSymbolAddress((void**)&Qh,   g_Qh);   cudaGetSymbolAddress((void**)&Kh,   g_Kh);
    cudaGetSymbolAddress((void**)&Vh,   g_Vh);
    cudaGetSymbolAddress((void**)&attn, g_attn); cudaGetSymbolAddress((void**)&x1,   g_x1);
    cudaGetSymbolAddress((void**)&x1h,  g_x1h);  cudaGetSymbolAddress((void**)&x1l,  g_x1l);
    cudaGetSymbolAddress((void**)&y,    g_y);
    cudaGetSymbolAddress((void**)&Wqt,  g_Wqt);  cudaGetSymbolAddress((void**)&Wkt,  g_Wkt);
    cudaGetSymbolAddress((void**)&Wvt,  g_Wvt);
    cudaGetSymbolAddress((void**)&Woth, g_Woth); cudaGetSymbolAddress((void**)&Wotl, g_Wotl);

    const int smem_g1 = 2 * 1 * (128 + 128) * 40 * 2;   // 40960
    const int smem_g3 = 2 * 2 * (128 + 128) * 40 * 2;   // 81920
    const int smem_fl = (FBQ * FLDS + 4 * FBK * FLDS) * 2 + 2 * 64 * 4;  // 55808
    cudaFuncSetAttribute((const void*)mma_gemm<128, 1, true,  true >,
                         cudaFuncAttributeMaxDynamicSharedMemorySize, smem_g1);
    cudaFuncSetAttribute((const void*)mma_gemm<128, 3, false, true >,
                         cudaFuncAttributeMaxDynamicSharedMemorySize, smem_g3);
    cudaFuncSetAttribute((const void*)flash_mma,
                         cudaFuncAttributeMaxDynamicSharedMemorySize, smem_fl);

    const float invs = 0.04419417382415922f;  // 1/sqrt(512)

    cvt_bf16<<<(MROWS * DD) / (256 * 8), 256>>>(Q, Qb);
    cvt_bf16<<<(MROWS * DD) / (256 * 8), 256>>>(K, Kb);
    dim3 twg(16, 16), twb(32, 8);
    transpose_w<<<twg, twb>>>(Wq, Wqt, nullptr);
    transpose_w<<<twg, twb>>>(Wk, Wkt, nullptr);
    transpose_w<<<twg, twb>>>(Wv, Wvt, nullptr);
    transpose_w<<<twg, twb>>>(Wo, Woth, Wotl);

    // projections (Qh pre-scaled by 1/sqrt(D))
    dim3 pg(DD / 128, MROWS / 128);
    mma_gemm<128, 1, true, true><<<pg, 256, smem_g1>>>(
        Qb, nullptr, DD, Wqt, nullptr, DD, Qh, DD, bq, invs, DD);
    mma_gemm<128, 1, true, true><<<pg, 256, smem_g1>>>(
        Kb, nullptr, DD, Wkt, nullptr, DD, Kh, DD, bk, 1.0f, DD);
    mma_gemm<128, 1, true, true><<<pg, 256, smem_g1>>>(
        Kb, nullptr, DD, Wvt, nullptr, DD, Vh, DD, bv, 1.0f, DD);

    // fused attention
    flash_mma<<<dim3(LQ / FBQ, BHN), 256, smem_fl>>>(Qh, Kh, Vh, pad, attn);

    // residual + LN (also emits hi/lo split of x1 for the Wo GEMM)
    add_ln<<<MROWS, 128>>>(Q, attn, g0, b0, x1, x1h, x1l, 0);

    // Wo GEMM in 3-term bf16 hi/lo split (accuracy-critical path)
    mma_gemm<128, 3, false, true><<<pg, 256, smem_g3>>>(
        x1h, x1l, DD, Woth, Wotl, DD, y, DD, bo, 1.0f, DD);

    add_ln<<<MROWS, 128>>>(x1, y, g1, b1, out, nullptr, nullptr, 1);
}

// round 6
// speedup vs baseline: 4.7070x; 1.0932x over previous
#include <cuda_runtime.h>
#include <cuda_bf16.h>
#include <cstdint>
#include <math.h>

#define BB 4
#define LQ 2048
#define LK 2048
#define DD 512
#define HH 8
#define DH 64
#define MROWS (BB * LQ)            // 8192
#define BHN  (BB * HH)             // 32
#define KVLD 1024                  // packed KV row stride (K cols 0-511, V cols 512-1023)

// ===================== scratch (static device globals) ======================
__device__ __nv_bfloat16 g_Qb [(size_t)MROWS * DD];
__device__ __nv_bfloat16 g_Kb [(size_t)MROWS * DD];
__device__ __nv_bfloat16 g_Qh [(size_t)MROWS * DD];
__device__ __nv_bfloat16 g_KVh[(size_t)MROWS * KVLD];
__device__ float         g_attn[(size_t)MROWS * DD];
__device__ float         g_x1 [(size_t)MROWS * DD];
__device__ __nv_bfloat16 g_x1h[(size_t)MROWS * DD];
__device__ __nv_bfloat16 g_x1l[(size_t)MROWS * DD];
__device__ float         g_y  [(size_t)MROWS * DD];
__device__ __nv_bfloat16 g_Wqt [(size_t)DD * DD];
__device__ __nv_bfloat16 g_Wkvt[(size_t)2 * DD * DD];   // rows 0-511: Wk^T, 512-1023: Wv^T
__device__ __nv_bfloat16 g_Woth[(size_t)DD * DD];
__device__ __nv_bfloat16 g_Wotl[(size_t)DD * DD];

// ===================== low-level helpers (sm_80+ only) ======================
__device__ __forceinline__ uint32_t smem_u32(const void* p) {
    uint32_t a;
    asm("{ .reg .u64 t; cvta.to.shared.u64 t, %1; cvt.u32.u64 %0, t; }"
        : "=r"(a) : "l"(p));
    return a;
}
__device__ __forceinline__ void cp_async16(uint32_t dst, const void* src) {
    asm volatile("cp.async.cg.shared.global [%0], [%1], 16;"
                 :: "r"(dst), "l"(src) : "memory");
}
#define CP_COMMIT() asm volatile("cp.async.commit_group;" ::: "memory")

__device__ __forceinline__ void ldm_x4(uint32_t* r, uint32_t addr) {
    asm volatile("ldmatrix.sync.aligned.m8n8.x4.shared.b16 {%0,%1,%2,%3}, [%4];"
                 : "=r"(r[0]), "=r"(r[1]), "=r"(r[2]), "=r"(r[3]) : "r"(addr));
}
__device__ __forceinline__ void ldm_x4_t(uint32_t* r, uint32_t addr) {
    asm volatile("ldmatrix.sync.aligned.m8n8.x4.trans.shared.b16 {%0,%1,%2,%3}, [%4];"
                 : "=r"(r[0]), "=r"(r[1]), "=r"(r[2]), "=r"(r[3]) : "r"(addr));
}
__device__ __forceinline__ void ldm_x2(uint32_t* r, uint32_t addr) {
    asm volatile("ldmatrix.sync.aligned.m8n8.x2.shared.b16 {%0,%1}, [%2];"
                 : "=r"(r[0]), "=r"(r[1]) : "r"(addr));
}
__device__ __forceinline__ void mma_bf16(float* d, const uint32_t* a, const uint32_t* b) {
    asm volatile(
        "mma.sync.aligned.m16n8k16.row.col.f32.bf16.bf16.f32 "
        "{%0,%1,%2,%3}, {%4,%5,%6,%7}, {%8,%9}, {%0,%1,%2,%3};"
        : "+f"(d[0]), "+f"(d[1]), "+f"(d[2]), "+f"(d[3])
        : "r"(a[0]), "r"(a[1]), "r"(a[2]), "r"(a[3]), "r"(b[0]), "r"(b[1]));
}
__device__ __forceinline__ uint32_t packbf(float a, float b) {
    __nv_bfloat162 t = __floats2bfloat162_rn(a, b);
    return *(uint32_t*)&t;
}
__device__ __forceinline__ float fexp2(float x) {
    float y;
    asm("ex2.approx.f32 %0, %1;" : "=f"(y) : "f"(x));
    return y;
}

// ===================== generic warp-MMA GEMM ================================
// D[128, BN-tile of N] = sum_K A[128,K] * B[N,K]^T  (bf16 in, fp32 accum)
// TERMS==3: A = Ahi+Alo, B = Bhi+Blo; computes hi*hi + hi*lo + lo*hi.
// bias2: if non-null, columns >= 512 use bias2[c-512] (packed KV projection).
template<int BN, int TERMS, bool OUT_BF16, bool HAS_BIAS>
__global__ __launch_bounds__(256)
void mma_gemm(const __nv_bfloat16* __restrict__ A,  const __nv_bfloat16* __restrict__ Alo,
              long long lda,
              const __nv_bfloat16* __restrict__ Bm, const __nv_bfloat16* __restrict__ Blo,
              long long ldb,
              void* __restrict__ Cout, long long ldc,
              const float* __restrict__ bias, const float* __restrict__ bias2,
              float outScale, int Ksz)
{
    constexpr int NTm   = (TERMS == 3) ? 2 : 1;
    constexpr int LDS   = 40;                  // padded row (elements): 80B stride
    constexpr int A_ELE = 128 * LDS;
    constexpr int B_ELE = BN * LDS;
    constexpr int STAGE = NTm * (A_ELE + B_ELE);
    constexpr int WN    = BN / 4;
    constexpr int NT_   = WN / 8;

    extern __shared__ __align__(16) __nv_bfloat16 sm_[];
    const int tid = threadIdx.x, wid = tid >> 5, lane = tid & 31;
    const int warp_m = wid & 1, warp_n = wid >> 1;
    const int m0 = blockIdx.y * 128, n0b = blockIdx.x * BN;

    const __nv_bfloat16* Ab  = A  + (long long)m0  * lda;
    const __nv_bfloat16* Bb  = Bm + (long long)n0b * ldb;
    const __nv_bfloat16* Abl = (TERMS == 3) ? (Alo + (long long)m0  * lda) : nullptr;
    const __nv_bfloat16* Bbl = (TERMS == 3) ? (Blo + (long long)n0b * ldb) : nullptr;

    const uint32_t sbase = smem_u32(sm_);

    float acc[4][NT_][4];
#pragma unroll
    for (int i = 0; i < 4; i++)
#pragma unroll
        for (int j = 0; j < NT_; j++)
#pragma unroll
            for (int k = 0; k < 4; k++) acc[i][j][k] = 0.f;

    auto load_stage = [&](int kt, int s) {
        const int koff = kt * 32;
        const uint32_t stA = sbase + (uint32_t)(s * STAGE) * 2;
        const uint32_t stB = stA + (uint32_t)(NTm * A_ELE) * 2;
#pragma unroll
        for (int i = tid; i < 512; i += 256) {
            int r = i >> 2, c = i & 3;
            cp_async16(stA + (uint32_t)(r * LDS + c * 8) * 2,
                       Ab + (long long)r * lda + koff + c * 8);
        }
        if (TERMS == 3) {
#pragma unroll
            for (int i = tid; i < 512; i += 256) {
                int r = i >> 2, c = i & 3;
                cp_async16(stA + (uint32_t)(A_ELE + r * LDS + c * 8) * 2,
                           Abl + (long long)r * lda + koff + c * 8);
            }
        }
#pragma unroll
        for (int i = tid; i < BN * 4; i += 256) {
            int r = i >> 2, c = i & 3;
            cp_async16(stB + (uint32_t)(r * LDS + c * 8) * 2,
                       Bb + (long long)r * ldb + koff + c * 8);
        }
        if (TERMS == 3) {
#pragma unroll
            for (int i = tid; i < BN * 4; i += 256) {
                int r = i >> 2, c = i & 3;
                cp_async16(stB + (uint32_t)(B_ELE + r * LDS + c * 8) * 2,
                           Bbl + (long long)r * ldb + koff + c * 8);
            }
        }
        CP_COMMIT();
    };

    auto compute_stage = [&](int s) {
        const uint32_t aBase0 = sbase + (uint32_t)(s * STAGE) * 2;
        const uint32_t bBase0 = aBase0 + (uint32_t)(NTm * A_ELE) * 2;
#pragma unroll
        for (int t = 0; t < TERMS; t++) {
            const uint32_t aB = aBase0 + ((t == 2) ? (uint32_t)A_ELE * 2 : 0u);
            const uint32_t bB = bBase0 + ((t == 1) ? (uint32_t)B_ELE * 2 : 0u);
#pragma unroll
            for (int ks = 0; ks < 2; ks++) {
                uint32_t af[4][4], bf[NT_][2];
#pragma unroll
                for (int mt = 0; mt < 4; mt++) {
                    uint32_t addr = aB + (uint32_t)(
                        (warp_m * 64 + mt * 16 + (lane & 15)) * LDS
                        + ks * 16 + ((lane >> 4) << 3)) * 2;
                    ldm_x4(af[mt], addr);
                }
#pragma unroll
                for (int nt = 0; nt < NT_; nt++) {
                    uint32_t addr = bB + (uint32_t)(
                        (warp_n * WN + nt * 8 + (lane & 7)) * LDS
                        + ks * 16 + (((lane >> 3) & 1) << 3)) * 2;
                    ldm_x2(bf[nt], addr);
                }
#pragma unroll
                for (int mt = 0; mt < 4; mt++)
#pragma unroll
                    for (int nt = 0; nt < NT_; nt++)
                        mma_bf16(acc[mt][nt], af[mt], bf[nt]);
            }
        }
    };

    const int KT = Ksz >> 5;
    load_stage(0, 0);
    for (int kt = 0; kt < KT; kt++) {
        if (kt + 1 < KT) {
            load_stage(kt + 1, (kt + 1) & 1);
            asm volatile("cp.async.wait_group 1;" ::: "memory");
        } else {
            asm volatile("cp.async.wait_group 0;" ::: "memory");
        }
        __syncthreads();
        compute_stage(kt & 1);
        __syncthreads();
    }

    // epilogue
#pragma unroll
    for (int mt = 0; mt < 4; mt++) {
        const int rb = m0 + warp_m * 64 + mt * 16 + (lane >> 2);
#pragma unroll
        for (int nt = 0; nt < NT_; nt++) {
            const int c0 = n0b + warp_n * WN + nt * 8 + (lane & 3) * 2;
            float bx = 0.f, by = 0.f;
            if (HAS_BIAS) {
                if (bias2 && c0 >= 512) { bx = bias2[c0 - 512]; by = bias2[c0 - 511]; }
                else                    { bx = bias[c0];        by = bias[c0 + 1];    }
            }
#pragma unroll
            for (int half = 0; half < 2; half++) {
                const int r = rb + half * 8;
                float x0 = (acc[mt][nt][half * 2 + 0] + bx) * outScale;
                float x1 = (acc[mt][nt][half * 2 + 1] + by) * outScale;
                if (OUT_BF16) {
                    __nv_bfloat16* C = (__nv_bfloat16*)Cout + (long long)r * ldc + c0;
                    *(__nv_bfloat162*)C = __floats2bfloat162_rn(x0, x1);
                } else {
                    float* C = (float*)Cout + (long long)r * ldc + c0;
                    float2 v; v.x = x0; v.y = x1;
                    *(float2*)C = v;
                }
            }
        }
    }
}

// ===================== fused flash attention (mma.sync) =====================
// Grid: (LQ/128, BHN). 256 threads = 8 warps; warp w owns rows 16w..16w+15.
// K/V loaded in 128-key stages (double-buffered); two 64-key compute subtiles
// per stage. Scores arrive pre-scaled by log2e -> softmax uses ex2.approx.
#define FBQ 128
#define FSK 128      // keys per load stage
#define FLDS 72      // padded row: 144 B stride -> ldmatrix conflict-free

__global__ __launch_bounds__(256, 1)
void flash_mma(const __nv_bfloat16* __restrict__ Qh,
               const __nv_bfloat16* __restrict__ KVh,
               const int* __restrict__ pad,
               float* __restrict__ Out)
{
    extern __shared__ __align__(16) char fsm[];
    __nv_bfloat16* Qs = (__nv_bfloat16*)fsm;            // 128*72
    __nv_bfloat16* Ks = Qs + FBQ * FLDS;                // 2 * 128*72
    __nv_bfloat16* Vs = Ks + 2 * FSK * FLDS;            // 2 * 128*72
    int*           Ms = (int*)(Vs + 2 * FSK * FLDS);    // 2 * 128

    const int tid = threadIdx.x, wid = tid >> 5, lane = tid & 31;
    const int q0 = blockIdx.x * FBQ;
    const int z = blockIdx.y, b = z >> 3, h = z & 7;
    const uint32_t sQ = smem_u32(Qs), sK = smem_u32(Ks);
    const uint32_t sV = smem_u32(Vs), sM = smem_u32(Ms);

    const __nv_bfloat16* Qp = Qh + ((size_t)(b * LQ + q0)) * DD + h * DH;
    const __nv_bfloat16* Kp = KVh + ((size_t)b * LK) * KVLD + h * DH;        // K cols
    const __nv_bfloat16* Vp = KVh + ((size_t)b * LK) * KVLD + 512 + h * DH;  // V cols
    const int* pp = pad + b * LK;

    // Q tile -> smem
#pragma unroll
    for (int i = tid; i < 1024; i += 256) {
        int r = i >> 3, c = i & 7;
        cp_async16(sQ + (uint32_t)(r * FLDS + c * 8) * 2, Qp + (size_t)r * DD + c * 8);
    }
    CP_COMMIT();

    auto load_kv = [&](int st, int s) {
        const int k0 = st * FSK;
        const uint32_t kb = sK + (uint32_t)(s * FSK * FLDS) * 2;
        const uint32_t vb = sV + (uint32_t)(s * FSK * FLDS) * 2;
#pragma unroll
        for (int i = tid; i < 1024; i += 256) {
            int r = i >> 3, c = i & 7;
            cp_async16(kb + (uint32_t)(r * FLDS + c * 8) * 2,
                       Kp + (size_t)(k0 + r) * KVLD + c * 8);
            cp_async16(vb + (uint32_t)(r * FLDS + c * 8) * 2,
                       Vp + (size_t)(k0 + r) * KVLD + c * 8);
        }
        if (tid < 32)
            cp_async16(sM + (uint32_t)(s * FSK + tid * 4) * 4, pp + k0 + tid * 4);
        CP_COMMIT();
    };

    load_kv(0, 0);

    uint32_t qf[4][4];
    float o[8][4];
#pragma unroll
    for (int i = 0; i < 8; i++)
#pragma unroll
        for (int j = 0; j < 4; j++) o[i][j] = 0.f;
    float m0 = -1e30f, m1 = -1e30f, l0 = 0.f, l1 = 0.f;

    const int NST = LK / FSK;   // 16
    for (int st = 0; st < NST; st++) {
        const int s = st & 1;
        if (st + 1 < NST) {
            load_kv(st + 1, s ^ 1);
            asm volatile("cp.async.wait_group 1;" ::: "memory");
        } else {
            asm volatile("cp.async.wait_group 0;" ::: "memory");
        }
        __syncthreads();
        if (st == 0) {
#pragma unroll
            for (int ks = 0; ks < 4; ks++) {
                uint32_t addr = sQ + (uint32_t)(
                    (wid * 16 + (lane & 15)) * FLDS + ks * 16 + ((lane >> 4) << 3)) * 2;
                ldm_x4(qf[ks], addr);
            }
        }

#pragma unroll
        for (int hk = 0; hk < 2; hk++) {
            const uint32_t kb = sK + (uint32_t)((s * FSK + hk * 64) * FLDS) * 2;
            const uint32_t vb = sV + (uint32_t)((s * FSK + hk * 64) * FLDS) * 2;
            const int* mskp = Ms + s * FSK + hk * 64;

            // ---- S = Q K^T (log2-domain scores) ----
            float sa[8][4];
#pragma unroll
            for (int i = 0; i < 8; i++)
#pragma unroll
                for (int j = 0; j < 4; j++) sa[i][j] = 0.f;
#pragma unroll
            for (int ks = 0; ks < 4; ks++) {
                uint32_t bk[8][2];
#pragma unroll
                for (int np = 0; np < 4; np++) {
                    uint32_t r4[4];
                    uint32_t addr = kb + (uint32_t)(
                        (np * 16 + (lane & 15)) * FLDS + ks * 16 + ((lane >> 4) << 3)) * 2;
                    ldm_x4(r4, addr);
                    bk[2 * np][0] = r4[0]; bk[2 * np][1] = r4[2];
                    bk[2 * np + 1][0] = r4[1]; bk[2 * np + 1][1] = r4[3];
                }
#pragma unroll
                for (int nt = 0; nt < 8; nt++) mma_bf16(sa[nt], qf[ks], bk[nt]);
            }

            // ---- masked online softmax (base-2) ----
            const int cb = (lane & 3) * 2;
            int mk0[8], mk1[8];
#pragma unroll
            for (int nt = 0; nt < 8; nt++) {
                mk0[nt] = mskp[nt * 8 + cb];
                mk1[nt] = mskp[nt * 8 + cb + 1];
            }
            float mx0 = -1e30f, mx1 = -1e30f;
#pragma unroll
            for (int nt = 0; nt < 8; nt++) {
                if (mk0[nt]) { mx0 = fmaxf(mx0, sa[nt][0]); mx1 = fmaxf(mx1, sa[nt][2]); }
                if (mk1[nt]) { mx0 = fmaxf(mx0, sa[nt][1]); mx1 = fmaxf(mx1, sa[nt][3]); }
            }
            mx0 = fmaxf(mx0, __shfl_xor_sync(~0u, mx0, 1));
            mx0 = fmaxf(mx0, __shfl_xor_sync(~0u, mx0, 2));
            mx1 = fmaxf(mx1, __shfl_xor_sync(~0u, mx1, 1));
            mx1 = fmaxf(mx1, __shfl_xor_sync(~0u, mx1, 2));
            const float mn0 = fmaxf(m0, mx0), mn1 = fmaxf(m1, mx1);
            const float al0 = fexp2(m0 - mn0), al1 = fexp2(m1 - mn1);
            m0 = mn0; m1 = mn1;
            float rs0 = 0.f, rs1 = 0.f;
#pragma unroll
            for (int nt = 0; nt < 8; nt++) {
                sa[nt][0] = mk0[nt] ? fexp2(sa[nt][0] - mn0) : 0.f;
                sa[nt][1] = mk1[nt] ? fexp2(sa[nt][1] - mn0) : 0.f;
                sa[nt][2] = mk0[nt] ? fexp2(sa[nt][2] - mn1) : 0.f;
                sa[nt][3] = mk1[nt] ? fexp2(sa[nt][3] - mn1) : 0.f;
                rs0 += sa[nt][0] + sa[nt][1];
                rs1 += sa[nt][2] + sa[nt][3];
            }
            rs0 += __shfl_xor_sync(~0u, rs0, 1); rs0 += __shfl_xor_sync(~0u, rs0, 2);
            rs1 += __shfl_xor_sync(~0u, rs1, 1); rs1 += __shfl_xor_sync(~0u, rs1, 2);
            l0 = l0 * al0 + rs0;
            l1 = l1 * al1 + rs1;
#pragma unroll
            for (int nt = 0; nt < 8; nt++) {
                o[nt][0] *= al0; o[nt][1] *= al0;
                o[nt][2] *= al1; o[nt][3] *= al1;
            }

            // ---- O += P V ----
#pragma unroll
            for (int ks = 0; ks < 4; ks++) {
                uint32_t pa[4];
                pa[0] = packbf(sa[2 * ks][0],     sa[2 * ks][1]);
                pa[1] = packbf(sa[2 * ks][2],     sa[2 * ks][3]);
                pa[2] = packbf(sa[2 * ks + 1][0], sa[2 * ks + 1][1]);
                pa[3] = packbf(sa[2 * ks + 1][2], sa[2 * ks + 1][3]);
#pragma unroll
                for (int np = 0; np < 4; np++) {
                    uint32_t r4[4];
                    uint32_t addr = vb + (uint32_t)(
                        (ks * 16 + (lane & 15)) * FLDS + np * 16 + ((lane >> 4) << 3)) * 2;
                    ldm_x4_t(r4, addr);
                    mma_bf16(o[2 * np],     pa, r4);
                    mma_bf16(o[2 * np + 1], pa, r4 + 2);
                }
            }
        }
        __syncthreads();
    }

    // ---- write O ----
    const float inv0 = (l0 > 0.f) ? 1.f / l0 : 0.f;
    const float inv1 = (l1 > 0.f) ? 1.f / l1 : 0.f;
    const int r0g = q0 + wid * 16 + (lane >> 2);
    float* ob0 = Out + ((size_t)(b * LQ + r0g)) * DD + h * DH + (lane & 3) * 2;
    float* ob1 = ob0 + (size_t)8 * DD;
#pragma unroll
    for (int nt = 0; nt < 8; nt++) {
        float2 v0; v0.x = o[nt][0] * inv0; v0.y = o[nt][1] * inv0;
        float2 v1; v1.x = o[nt][2] * inv1; v1.y = o[nt][3] * inv1;
        *(float2*)(ob0 + nt * 8) = v0;
        *(float2*)(ob1 + nt * 8) = v1;
    }
}

// ===================== small helper kernels =================================
__global__ __launch_bounds__(256) void cvt_bf16(const float* __restrict__ x,
                                                __nv_bfloat16* __restrict__ y)
{
    size_t i = ((size_t)blockIdx.x * 256 + threadIdx.x) * 8;
    float4 a = *(const float4*)(x + i), b = *(const float4*)(x + i + 4);
    __nv_bfloat162 r0 = __floats2bfloat162_rn(a.x, a.y);
    __nv_bfloat162 r1 = __floats2bfloat162_rn(a.z, a.w);
    __nv_bfloat162 r2 = __floats2bfloat162_rn(b.x, b.y);
    __nv_bfloat162 r3 = __floats2bfloat162_rn(b.z, b.w);
    uint4 o;
    o.x = *(uint32_t*)&r0; o.y = *(uint32_t*)&r1;
    o.z = *(uint32_t*)&r2; o.w = *(uint32_t*)&r3;
    *(uint4*)(y + i) = o;
}

// fused weight transposes: z=0 Wq->Wqt, z=1 Wk->Wkvt[0:512], z=2 Wv->Wkvt[512:],
// z=3 Wo->Woth+Wotl
__global__ void tw_fused(const float* __restrict__ Wq, const float* __restrict__ Wk,
                         const float* __restrict__ Wv, const float* __restrict__ Wo,
                         __nv_bfloat16* __restrict__ Wqt, __nv_bfloat16* __restrict__ Wkvt,
                         __nv_bfloat16* __restrict__ Woth, __nv_bfloat16* __restrict__ Wotl)
{
    __shared__ float t[32][33];
    const int zz = blockIdx.z;
    const float* W = (zz == 0) ? Wq : (zz == 1) ? Wk : (zz == 2) ? Wv : Wo;
    __nv_bfloat16* Th = (zz == 0) ? Wqt : (zz == 1) ? Wkvt
                       : (zz == 2) ? (Wkvt + (size_t)512 * DD) : Woth;
    __nv_bfloat16* Tl = (zz == 3) ? Wotl : nullptr;

    const int x = blockIdx.x * 32, y = blockIdx.y * 32;
    const int tx = threadIdx.x, ty = threadIdx.y;
    for (int i = ty; i < 32; i += 8)
        t[i][tx] = W[(size_t)(y + i) * DD + x + tx];
    __syncthreads();
    for (int i = ty; i < 32; i += 8) {
        float v = t[tx][i];
        __nv_bfloat16 hb = __float2bfloat16(v);
        Th[(size_t)(x + i) * DD + y + tx] = hb;
        if (Tl) Tl[(size_t)(x + i) * DD + y + tx] =
            __float2bfloat16(v - __bfloat162float(hb));
    }
}

// residual + layernorm. relu_mode=0: t=X+Y; 1: t=X+relu(Y).
// Optionally also emits hi/lo bf16 split of the result.
__global__ __launch_bounds__(128) void add_ln(
    const float* __restrict__ X, const float* __restrict__ Y,
    const float* __restrict__ g, const float* __restrict__ beta,
    float* __restrict__ out, __nv_bfloat16* __restrict__ ohi,
    __nv_bfloat16* __restrict__ olo, int relu_mode)
{
    const int row = blockIdx.x;
    const int tid = threadIdx.x;
    const size_t base = (size_t)row * DD;
    const int c4 = tid * 4;

    float4 xa = *(const float4*)(X + base + c4);
    float4 ya = *(const float4*)(Y + base + c4);
    float v[4];
    v[0] = relu_mode ? (xa.x + fmaxf(ya.x, 0.f)) : (xa.x + ya.x);
    v[1] = relu_mode ? (xa.y + fmaxf(ya.y, 0.f)) : (xa.y + ya.y);
    v[2] = relu_mode ? (xa.z + fmaxf(ya.z, 0.f)) : (xa.z + ya.z);
    v[3] = relu_mode ? (xa.w + fmaxf(ya.w, 0.f)) : (xa.w + ya.w);
    float s = 0.f, s2 = 0.f;
#pragma unroll
    for (int i = 0; i < 4; i++) { s += v[i]; s2 = fmaf(v[i], v[i], s2); }
#pragma unroll
    for (int o = 16; o > 0; o >>= 1) {
        s  += __shfl_xor_sync(~0u, s, o);
        s2 += __shfl_xor_sync(~0u, s2, o);
    }
    __shared__ float sh[8];
    int w = tid >> 5;
    if ((tid & 31) == 0) { sh[w] = s; sh[4 + w] = s2; }
    __syncthreads();
    if (tid == 0) {
        float S1 = sh[0] + sh[1] + sh[2] + sh[3];
        float S2 = sh[4] + sh[5] + sh[6] + sh[7];
        float mean = S1 * (1.f / DD);
        float var  = S2 * (1.f / DD) - mean * mean;
        sh[0] = mean;
        sh[1] = rsqrtf(var + 1e-5f);
    }
    __syncthreads();
    const float mean = sh[0], rstd = sh[1];
    const float4 gg = *(const float4*)(g + c4);
    const float4 bb = *(const float4*)(beta + c4);
    float4 ov;
    ov.x = (v[0] - mean) * rstd * gg.x + bb.x;
    ov.y = (v[1] - mean) * rstd * gg.y + bb.y;
    ov.z = (v[2] - mean) * rstd * gg.z + bb.z;
    ov.w = (v[3] - mean) * rstd * gg.w + bb.w;
    *(float4*)(out + base + c4) = ov;
    if (ohi) {
        float t[4] = {ov.x, ov.y, ov.z, ov.w};
        __nv_bfloat16 hb[4], lb[4];
#pragma unroll
        for (int i = 0; i < 4; i++) {
            hb[i] = __float2bfloat16(t[i]);
            lb[i] = __float2bfloat16(t[i] - __bfloat162float(hb[i]));
        }
        __nv_bfloat162 h0 = {hb[0], hb[1]}, h1 = {hb[2], hb[3]};
        __nv_bfloat162 l0 = {lb[0], lb[1]}, l1 = {lb[2], lb[3]};
        uint2 ho = {*(uint32_t*)&h0, *(uint32_t*)&h1};
        uint2 lo = {*(uint32_t*)&l0, *(uint32_t*)&l1};
        *(uint2*)(ohi + base + c4) = ho;
        *(uint2*)(olo + base + c4) = lo;
    }
}

// ===================== launch ===============================================
extern "C" void kernel_launch(void* const* d_in, const int* in_sizes, int n_in,
                              void* d_out, int out_size)
{
    const float* Q   = (const float*)d_in[0];
    const float* K   = (const float*)d_in[1];
    const int*   pad = (const int*)  d_in[2];
    const float* Wq  = (const float*)d_in[3];  const float* bq = (const float*)d_in[4];
    const float* Wk  = (const float*)d_in[5];  const float* bk = (const float*)d_in[6];
    const float* Wv  = (const float*)d_in[7];  const float* bv = (const float*)d_in[8];
    const float* Wo  = (const float*)d_in[9];  const float* bo = (const float*)d_in[10];
    const float* g0  = (const float*)d_in[11]; const float* b0 = (const float*)d_in[12];
    const float* g1  = (const float*)d_in[13]; const float* b1 = (const float*)d_in[14];
    float* out = (float*)d_out;

    __nv_bfloat16 *Qb, *Kb, *Qh, *KVh, *x1h, *x1l, *Wqt, *Wkvt, *Woth, *Wotl;
    float *attn, *x1, *y;
    cudaGetSymbolAddress((void**)&Qb,   g_Qb);   cudaGetSymbolAddress((void**)&Kb,   g_Kb);
    cudaGetSymbolAddress((void**)&Qh,   g_Qh);   cudaGetSymbolAddress((void**)&KVh,  g_KVh);
    cudaGetSymbolAddress((void**)&attn, g_attn); cudaGetSymbolAddress((void**)&x1,   g_x1);
    cudaGetSymbolAddress((void**)&x1h,  g_x1h);  cudaGetSymbolAddress((void**)&x1l,  g_x1l);
    cudaGetSymbolAddress((void**)&y,    g_y);
    cudaGetSymbolAddress((void**)&Wqt,  g_Wqt);  cudaGetSymbolAddress((void**)&Wkvt, g_Wkvt);
    cudaGetSymbolAddress((void**)&Woth, g_Woth); cudaGetSymbolAddress((void**)&Wotl, g_Wotl);

    const int smem_g1 = 2 * 1 * (128 + 128) * 40 * 2;   // 40960
    const int smem_g3 = 2 * 2 * (128 + 128) * 40 * 2;   // 81920
    const int smem_fl = (FBQ * FLDS + 4 * FSK * FLDS) * 2 + 2 * FSK * 4;  // 93184
    cudaFuncSetAttribute((const void*)mma_gemm<128, 1, true,  true >,
                         cudaFuncAttributeMaxDynamicSharedMemorySize, smem_g1);
    cudaFuncSetAttribute((const void*)mma_gemm<128, 3, false, true >,
                         cudaFuncAttributeMaxDynamicSharedMemorySize, smem_g3);
    cudaFuncSetAttribute((const void*)flash_mma,
                         cudaFuncAttributeMaxDynamicSharedMemorySize, smem_fl);

    // 1/sqrt(512) * log2(e): scores land in log2 domain for ex2-based softmax
    const float qscale = 0.04419417382415922f * 1.4426950408889634f;

    // launches 0,1: input conversions
    cvt_bf16<<<(MROWS * DD) / (256 * 8), 256>>>(Q, Qb);
    cvt_bf16<<<(MROWS * DD) / (256 * 8), 256>>>(K, Kb);
    // launch 2: all weight transposes
    tw_fused<<<dim3(16, 16, 4), dim3(32, 8)>>>(Wq, Wk, Wv, Wo, Wqt, Wkvt, Woth, Wotl);

    // launch 3: Q projection (pre-scaled)
    dim3 pgq(DD / 128, MROWS / 128);
    mma_gemm<128, 1, true, true><<<pgq, 256, smem_g1>>>(
        Qb, nullptr, DD, Wqt, nullptr, DD, Qh, DD, bq, nullptr, qscale, DD);
    // launch 4: fused K+V projection into packed KV (N = 1024)
    dim3 pgkv(KVLD / 128, MROWS / 128);
    mma_gemm<128, 1, true, true><<<pgkv, 256, smem_g1>>>(
        Kb, nullptr, DD, Wkvt, nullptr, DD, KVh, KVLD, bk, bv, 1.0f, DD);

    // launch 5: fused attention  (ncu -s 5 -c 1 profiles this one)
    flash_mma<<<dim3(LQ / FBQ, BHN), 256, smem_fl>>>(Qh, KVh, pad, attn);

    // launch 6: residual + LN (+ hi/lo split of x1)
    add_ln<<<MROWS, 128>>>(Q, attn, g0, b0, x1, x1h, x1l, 0);

    // launch 7: Wo GEMM, 3-term bf16 hi/lo split
    mma_gemm<128, 3, false, true><<<pgq, 256, smem_g3>>>(
        x1h, x1l, DD, Woth, Wotl, DD, y, DD, bo, nullptr, 1.0f, DD);

    // launch 8: final residual + LN
    add_ln<<<MROWS, 128>>>(x1, y, g1, b1, out, nullptr, nullptr, 1);
}

// round 7
// speedup vs baseline: 5.2811x; 1.1220x over previous
#include <cuda_runtime.h>
#include <cuda_bf16.h>
#include <cstdint>
#include <math.h>

#define BB 4
#define LQ 2048
#define LK 2048
#define DD 512
#define HH 8
#define DH 64
#define MROWS (BB * LQ)            // 8192
#define BHN  (BB * HH)             // 32
#define KVLD 1024                  // packed KV row stride (K cols 0-511, V cols 512-1023)

// ===================== scratch (static device globals) ======================
__device__ __nv_bfloat16 g_Qb [(size_t)MROWS * DD];
__device__ __nv_bfloat16 g_Kb [(size_t)MROWS * DD];
__device__ __nv_bfloat16 g_Qh [(size_t)MROWS * DD];
__device__ __nv_bfloat16 g_KVh[(size_t)MROWS * KVLD];
__device__ float         g_attn[(size_t)MROWS * DD];
__device__ float         g_x1 [(size_t)MROWS * DD];
__device__ __nv_bfloat16 g_x1h[(size_t)MROWS * DD];
__device__ __nv_bfloat16 g_x1l[(size_t)MROWS * DD];
__device__ float         g_y  [(size_t)MROWS * DD];
__device__ __nv_bfloat16 g_Wqt [(size_t)DD * DD];
__device__ __nv_bfloat16 g_Wkvt[(size_t)2 * DD * DD];   // rows 0-511: Wk^T, 512-1023: Wv^T
__device__ __nv_bfloat16 g_Woth[(size_t)DD * DD];
__device__ __nv_bfloat16 g_Wotl[(size_t)DD * DD];

// ===================== low-level helpers (sm_80+ only) ======================
__device__ __forceinline__ uint32_t smem_u32(const void* p) {
    uint32_t a;
    asm("{ .reg .u64 t; cvta.to.shared.u64 t, %1; cvt.u32.u64 %0, t; }"
        : "=r"(a) : "l"(p));
    return a;
}
__device__ __forceinline__ void cp_async16(uint32_t dst, const void* src) {
    asm volatile("cp.async.cg.shared.global [%0], [%1], 16;"
                 :: "r"(dst), "l"(src) : "memory");
}
#define CP_COMMIT() asm volatile("cp.async.commit_group;" ::: "memory")

__device__ __forceinline__ void ldm_x4(uint32_t* r, uint32_t addr) {
    asm volatile("ldmatrix.sync.aligned.m8n8.x4.shared.b16 {%0,%1,%2,%3}, [%4];"
                 : "=r"(r[0]), "=r"(r[1]), "=r"(r[2]), "=r"(r[3]) : "r"(addr));
}
__device__ __forceinline__ void ldm_x4_t(uint32_t* r, uint32_t addr) {
    asm volatile("ldmatrix.sync.aligned.m8n8.x4.trans.shared.b16 {%0,%1,%2,%3}, [%4];"
                 : "=r"(r[0]), "=r"(r[1]), "=r"(r[2]), "=r"(r[3]) : "r"(addr));
}
__device__ __forceinline__ void ldm_x2(uint32_t* r, uint32_t addr) {
    asm volatile("ldmatrix.sync.aligned.m8n8.x2.shared.b16 {%0,%1}, [%2];"
                 : "=r"(r[0]), "=r"(r[1]) : "r"(addr));
}
__device__ __forceinline__ void mma_bf16(float* d, const uint32_t* a, const uint32_t* b) {
    asm volatile(
        "mma.sync.aligned.m16n8k16.row.col.f32.bf16.bf16.f32 "
        "{%0,%1,%2,%3}, {%4,%5,%6,%7}, {%8,%9}, {%0,%1,%2,%3};"
        : "+f"(d[0]), "+f"(d[1]), "+f"(d[2]), "+f"(d[3])
        : "r"(a[0]), "r"(a[1]), "r"(a[2]), "r"(a[3]), "r"(b[0]), "r"(b[1]));
}
__device__ __forceinline__ uint32_t packbf(float a, float b) {
    __nv_bfloat162 t = __floats2bfloat162_rn(a, b);
    return *(uint32_t*)&t;
}
__device__ __forceinline__ float fexp2(float x) {
    float y;
    asm("ex2.approx.f32 %0, %1;" : "=f"(y) : "f"(x));
    return y;
}

// ===================== generic warp-MMA GEMM ================================
// D[128, BN-tile of N] = sum_K A[128,K] * B[N,K]^T  (bf16 in, fp32 accum)
// TERMS==3: A = Ahi+Alo, B = Bhi+Blo; computes hi*hi + hi*lo + lo*hi.
// NS: cp.async pipeline stages. NS==4 uses a single-barrier-per-k-step
// schedule (stage (kt+2)%4 was last read at compute(kt-2), which all warps
// finished before the barrier of iteration kt-1 -> overwrite is safe).
// bias2: if non-null, columns >= 512 use bias2[c-512] (packed KV projection).
template<int BN, int TERMS, bool OUT_BF16, bool HAS_BIAS, int NS>
__global__ __launch_bounds__(256)
void mma_gemm(const __nv_bfloat16* __restrict__ A,  const __nv_bfloat16* __restrict__ Alo,
              long long lda,
              const __nv_bfloat16* __restrict__ Bm, const __nv_bfloat16* __restrict__ Blo,
              long long ldb,
              void* __restrict__ Cout, long long ldc,
              const float* __restrict__ bias, const float* __restrict__ bias2,
              float outScale, int Ksz)
{
    constexpr int NTm   = (TERMS == 3) ? 2 : 1;
    constexpr int LDS   = 40;                  // padded row (elements): 80B stride
    constexpr int A_ELE = 128 * LDS;
    constexpr int B_ELE = BN * LDS;
    constexpr int STAGE = NTm * (A_ELE + B_ELE);
    constexpr int WN    = BN / 4;
    constexpr int NT_   = WN / 8;

    extern __shared__ __align__(16) __nv_bfloat16 sm_[];
    const int tid = threadIdx.x, wid = tid >> 5, lane = tid & 31;
    const int warp_m = wid & 1, warp_n = wid >> 1;
    const int m0 = blockIdx.y * 128, n0b = blockIdx.x * BN;

    const __nv_bfloat16* Ab  = A  + (long long)m0  * lda;
    const __nv_bfloat16* Bb  = Bm + (long long)n0b * ldb;
    const __nv_bfloat16* Abl = (TERMS == 3) ? (Alo + (long long)m0  * lda) : nullptr;
    const __nv_bfloat16* Bbl = (TERMS == 3) ? (Blo + (long long)n0b * ldb) : nullptr;

    const uint32_t sbase = smem_u32(sm_);

    float acc[4][NT_][4];
#pragma unroll
    for (int i = 0; i < 4; i++)
#pragma unroll
        for (int j = 0; j < NT_; j++)
#pragma unroll
            for (int k = 0; k < 4; k++) acc[i][j][k] = 0.f;

    auto load_stage = [&](int kt, int s) {
        const int koff = kt * 32;
        const uint32_t stA = sbase + (uint32_t)(s * STAGE) * 2;
        const uint32_t stB = stA + (uint32_t)(NTm * A_ELE) * 2;
#pragma unroll
        for (int i = tid; i < 512; i += 256) {
            int r = i >> 2, c = i & 3;
            cp_async16(stA + (uint32_t)(r * LDS + c * 8) * 2,
                       Ab + (long long)r * lda + koff + c * 8);
        }
        if (TERMS == 3) {
#pragma unroll
            for (int i = tid; i < 512; i += 256) {
                int r = i >> 2, c = i & 3;
                cp_async16(stA + (uint32_t)(A_ELE + r * LDS + c * 8) * 2,
                           Abl + (long long)r * lda + koff + c * 8);
            }
        }
#pragma unroll
        for (int i = tid; i < BN * 4; i += 256) {
            int r = i >> 2, c = i & 3;
            cp_async16(stB + (uint32_t)(r * LDS + c * 8) * 2,
                       Bb + (long long)r * ldb + koff + c * 8);
        }
        if (TERMS == 3) {
#pragma unroll
            for (int i = tid; i < BN * 4; i += 256) {
                int r = i >> 2, c = i & 3;
                cp_async16(stB + (uint32_t)(B_ELE + r * LDS + c * 8) * 2,
                           Bbl + (long long)r * ldb + koff + c * 8);
            }
        }
        CP_COMMIT();
    };

    auto compute_stage = [&](int s) {
        const uint32_t aBase0 = sbase + (uint32_t)(s * STAGE) * 2;
        const uint32_t bBase0 = aBase0 + (uint32_t)(NTm * A_ELE) * 2;
#pragma unroll
        for (int t = 0; t < TERMS; t++) {
            const uint32_t aB = aBase0 + ((t == 2) ? (uint32_t)A_ELE * 2 : 0u);
            const uint32_t bB = bBase0 + ((t == 1) ? (uint32_t)B_ELE * 2 : 0u);
#pragma unroll
            for (int ks = 0; ks < 2; ks++) {
                uint32_t af[4][4], bf[NT_][2];
#pragma unroll
                for (int mt = 0; mt < 4; mt++) {
                    uint32_t addr = aB + (uint32_t)(
                        (warp_m * 64 + mt * 16 + (lane & 15)) * LDS
                        + ks * 16 + ((lane >> 4) << 3)) * 2;
                    ldm_x4(af[mt], addr);
                }
#pragma unroll
                for (int nt = 0; nt < NT_; nt++) {
                    uint32_t addr = bB + (uint32_t)(
                        (warp_n * WN + nt * 8 + (lane & 7)) * LDS
                        + ks * 16 + (((lane >> 3) & 1) << 3)) * 2;
                    ldm_x2(bf[nt], addr);
                }
#pragma unroll
                for (int mt = 0; mt < 4; mt++)
#pragma unroll
                    for (int nt = 0; nt < NT_; nt++)
                        mma_bf16(acc[mt][nt], af[mt], bf[nt]);
            }
        }
    };

    const int KT = Ksz >> 5;
    if (NS == 4) {
        load_stage(0, 0);
        if (KT > 1) load_stage(1, 1);
        for (int kt = 0; kt < KT; kt++) {
            if (kt + 2 < KT) {
                load_stage(kt + 2, (kt + 2) & 3);
                asm volatile("cp.async.wait_group 2;" ::: "memory");
            } else if (kt + 1 < KT) {
                asm volatile("cp.async.wait_group 1;" ::: "memory");
            } else {
                asm volatile("cp.async.wait_group 0;" ::: "memory");
            }
            __syncthreads();
            compute_stage(kt & 3);
        }
    } else {
        load_stage(0, 0);
        for (int kt = 0; kt < KT; kt++) {
            if (kt + 1 < KT) {
                load_stage(kt + 1, (kt + 1) & 1);
                asm volatile("cp.async.wait_group 1;" ::: "memory");
            } else {
                asm volatile("cp.async.wait_group 0;" ::: "memory");
            }
            __syncthreads();
            compute_stage(kt & 1);
            __syncthreads();
        }
    }

    // epilogue
#pragma unroll
    for (int mt = 0; mt < 4; mt++) {
        const int rb = m0 + warp_m * 64 + mt * 16 + (lane >> 2);
#pragma unroll
        for (int nt = 0; nt < NT_; nt++) {
            const int c0 = n0b + warp_n * WN + nt * 8 + (lane & 3) * 2;
            float bx = 0.f, by = 0.f;
            if (HAS_BIAS) {
                if (bias2 && c0 >= 512) { bx = bias2[c0 - 512]; by = bias2[c0 - 511]; }
                else                    { bx = bias[c0];        by = bias[c0 + 1];    }
            }
#pragma unroll
            for (int half = 0; half < 2; half++) {
                const int r = rb + half * 8;
                float x0 = (acc[mt][nt][half * 2 + 0] + bx) * outScale;
                float x1 = (acc[mt][nt][half * 2 + 1] + by) * outScale;
                if (OUT_BF16) {
                    __nv_bfloat16* C = (__nv_bfloat16*)Cout + (long long)r * ldc + c0;
                    *(__nv_bfloat162*)C = __floats2bfloat162_rn(x0, x1);
                } else {
                    float* C = (float*)Cout + (long long)r * ldc + c0;
                    float2 v; v.x = x0; v.y = x1;
                    *(float2*)C = v;
                }
            }
        }
    }
}

// ===================== fused flash attention (mma.sync) =====================
// Grid: (LQ/128, BHN). 256 threads = 8 warps; warp w owns rows 16w..16w+15.
// K/V loaded in 128-key stages (double-buffered); two 64-key compute subtiles
// per stage. Scores arrive pre-scaled by log2e -> softmax uses ex2.approx.
// __launch_bounds__(256,2): 2 CTAs/SM (186 KB smem) to hide barrier/MMA latency.
#define FBQ 128
#define FSK 128      // keys per load stage
#define FLDS 72      // padded row: 144 B stride -> ldmatrix conflict-free

__global__ __launch_bounds__(256, 2)
void flash_mma(const __nv_bfloat16* __restrict__ Qh,
               const __nv_bfloat16* __restrict__ KVh,
               const int* __restrict__ pad,
               float* __restrict__ Out)
{
    extern __shared__ __align__(16) char fsm[];
    __nv_bfloat16* Qs = (__nv_bfloat16*)fsm;            // 128*72
    __nv_bfloat16* Ks = Qs + FBQ * FLDS;                // 2 * 128*72
    __nv_bfloat16* Vs = Ks + 2 * FSK * FLDS;            // 2 * 128*72
    int*           Ms = (int*)(Vs + 2 * FSK * FLDS);    // 2 * 128

    const int tid = threadIdx.x, wid = tid >> 5, lane = tid & 31;
    const int q0 = blockIdx.x * FBQ;
    const int z = blockIdx.y, b = z >> 3, h = z & 7;
    const uint32_t sQ = smem_u32(Qs), sK = smem_u32(Ks);
    const uint32_t sV = smem_u32(Vs), sM = smem_u32(Ms);

    const __nv_bfloat16* Qp = Qh + ((size_t)(b * LQ + q0)) * DD + h * DH;
    const __nv_bfloat16* Kp = KVh + ((size_t)b * LK) * KVLD + h * DH;        // K cols
    const __nv_bfloat16* Vp = KVh + ((size_t)b * LK) * KVLD + 512 + h * DH;  // V cols
    const int* pp = pad + b * LK;

    // Q tile -> smem
#pragma unroll
    for (int i = tid; i < 1024; i += 256) {
        int r = i >> 3, c = i & 7;
        cp_async16(sQ + (uint32_t)(r * FLDS + c * 8) * 2, Qp + (size_t)r * DD + c * 8);
    }
    CP_COMMIT();

    auto load_kv = [&](int st, int s) {
        const int k0 = st * FSK;
        const uint32_t kb = sK + (uint32_t)(s * FSK * FLDS) * 2;
        const uint32_t vb = sV + (uint32_t)(s * FSK * FLDS) * 2;
#pragma unroll
        for (int i = tid; i < 1024; i += 256) {
            int r = i >> 3, c = i & 7;
            cp_async16(kb + (uint32_t)(r * FLDS + c * 8) * 2,
                       Kp + (size_t)(k0 + r) * KVLD + c * 8);
            cp_async16(vb + (uint32_t)(r * FLDS + c * 8) * 2,
                       Vp + (size_t)(k0 + r) * KVLD + c * 8);
        }
        if (tid < 32)
            cp_async16(sM + (uint32_t)(s * FSK + tid * 4) * 4, pp + k0 + tid * 4);
        CP_COMMIT();
    };

    load_kv(0, 0);

    uint32_t qf[4][4];
    float o[8][4];
#pragma unroll
    for (int i = 0; i < 8; i++)
#pragma unroll
        for (int j = 0; j < 4; j++) o[i][j] = 0.f;
    float m0 = -1e30f, m1 = -1e30f, l0 = 0.f, l1 = 0.f;

    const int NST = LK / FSK;   // 16
    for (int st = 0; st < NST; st++) {
        const int s = st & 1;
        if (st + 1 < NST) {
            load_kv(st + 1, s ^ 1);
            asm volatile("cp.async.wait_group 1;" ::: "memory");
        } else {
            asm volatile("cp.async.wait_group 0;" ::: "memory");
        }
        __syncthreads();
        if (st == 0) {
#pragma unroll
            for (int ks = 0; ks < 4; ks++) {
                uint32_t addr = sQ + (uint32_t)(
                    (wid * 16 + (lane & 15)) * FLDS + ks * 16 + ((lane >> 4) << 3)) * 2;
                ldm_x4(qf[ks], addr);
            }
        }

#pragma unroll
        for (int hk = 0; hk < 2; hk++) {
            const uint32_t kb = sK + (uint32_t)((s * FSK + hk * 64) * FLDS) * 2;
            const uint32_t vb = sV + (uint32_t)((s * FSK + hk * 64) * FLDS) * 2;
            const int* mskp = Ms + s * FSK + hk * 64;

            // ---- S = Q K^T (log2-domain scores) ----
            float sa[8][4];
#pragma unroll
            for (int i = 0; i < 8; i++)
#pragma unroll
                for (int j = 0; j < 4; j++) sa[i][j] = 0.f;
#pragma unroll
            for (int ks = 0; ks < 4; ks++) {
                uint32_t bk[8][2];
#pragma unroll
                for (int np = 0; np < 4; np++) {
                    uint32_t r4[4];
                    uint32_t addr = kb + (uint32_t)(
                        (np * 16 + (lane & 15)) * FLDS + ks * 16 + ((lane >> 4) << 3)) * 2;
                    ldm_x4(r4, addr);
                    bk[2 * np][0] = r4[0]; bk[2 * np][1] = r4[2];
                    bk[2 * np + 1][0] = r4[1]; bk[2 * np + 1][1] = r4[3];
                }
#pragma unroll
                for (int nt = 0; nt < 8; nt++) mma_bf16(sa[nt], qf[ks], bk[nt]);
            }

            // ---- masked online softmax (base-2) ----
            const int cb = (lane & 3) * 2;
            int mk0[8], mk1[8];
#pragma unroll
            for (int nt = 0; nt < 8; nt++) {
                mk0[nt] = mskp[nt * 8 + cb];
                mk1[nt] = mskp[nt * 8 + cb + 1];
            }
            float mx0 = -1e30f, mx1 = -1e30f;
#pragma unroll
            for (int nt = 0; nt < 8; nt++) {
                if (mk0[nt]) { mx0 = fmaxf(mx0, sa[nt][0]); mx1 = fmaxf(mx1, sa[nt][2]); }
                if (mk1[nt]) { mx0 = fmaxf(mx0, sa[nt][1]); mx1 = fmaxf(mx1, sa[nt][3]); }
            }
            mx0 = fmaxf(mx0, __shfl_xor_sync(~0u, mx0, 1));
            mx0 = fmaxf(mx0, __shfl_xor_sync(~0u, mx0, 2));
            mx1 = fmaxf(mx1, __shfl_xor_sync(~0u, mx1, 1));
            mx1 = fmaxf(mx1, __shfl_xor_sync(~0u, mx1, 2));
            const float mn0 = fmaxf(m0, mx0), mn1 = fmaxf(m1, mx1);
            const float al0 = fexp2(m0 - mn0), al1 = fexp2(m1 - mn1);
            m0 = mn0; m1 = mn1;
            float rs0 = 0.f, rs1 = 0.f;
#pragma unroll
            for (int nt = 0; nt < 8; nt++) {
                sa[nt][0] = mk0[nt] ? fexp2(sa[nt][0] - mn0) : 0.f;
                sa[nt][1] = mk1[nt] ? fexp2(sa[nt][1] - mn0) : 0.f;
                sa[nt][2] = mk0[nt] ? fexp2(sa[nt][2] - mn1) : 0.f;
                sa[nt][3] = mk1[nt] ? fexp2(sa[nt][3] - mn1) : 0.f;
                rs0 += sa[nt][0] + sa[nt][1];
                rs1 += sa[nt][2] + sa[nt][3];
            }
            rs0 += __shfl_xor_sync(~0u, rs0, 1); rs0 += __shfl_xor_sync(~0u, rs0, 2);
            rs1 += __shfl_xor_sync(~0u, rs1, 1); rs1 += __shfl_xor_sync(~0u, rs1, 2);
            l0 = l0 * al0 + rs0;
            l1 = l1 * al1 + rs1;
#pragma unroll
            for (int nt = 0; nt < 8; nt++) {
                o[nt][0] *= al0; o[nt][1] *= al0;
                o[nt][2] *= al1; o[nt][3] *= al1;
            }

            // ---- O += P V ----
#pragma unroll
            for (int ks = 0; ks < 4; ks++) {
                uint32_t pa[4];
                pa[0] = packbf(sa[2 * ks][0],     sa[2 * ks][1]);
                pa[1] = packbf(sa[2 * ks][2],     sa[2 * ks][3]);
                pa[2] = packbf(sa[2 * ks + 1][0], sa[2 * ks + 1][1]);
                pa[3] = packbf(sa[2 * ks + 1][2], sa[2 * ks + 1][3]);
#pragma unroll
                for (int np = 0; np < 4; np++) {
                    uint32_t r4[4];
                    uint32_t addr = vb + (uint32_t)(
                        (ks * 16 + (lane & 15)) * FLDS + np * 16 + ((lane >> 4) << 3)) * 2;
                    ldm_x4_t(r4, addr);
                    mma_bf16(o[2 * np],     pa, r4);
                    mma_bf16(o[2 * np + 1], pa, r4 + 2);
                }
            }
        }
        __syncthreads();
    }

    // ---- write O ----
    const float inv0 = (l0 > 0.f) ? 1.f / l0 : 0.f;
    const float inv1 = (l1 > 0.f) ? 1.f / l1 : 0.f;
    const int r0g = q0 + wid * 16 + (lane >> 2);
    float* ob0 = Out + ((size_t)(b * LQ + r0g)) * DD + h * DH + (lane & 3) * 2;
    float* ob1 = ob0 + (size_t)8 * DD;
#pragma unroll
    for (int nt = 0; nt < 8; nt++) {
        float2 v0; v0.x = o[nt][0] * inv0; v0.y = o[nt][1] * inv0;
        float2 v1; v1.x = o[nt][2] * inv1; v1.y = o[nt][3] * inv1;
        *(float2*)(ob0 + nt * 8) = v0;
        *(float2*)(ob1 + nt * 8) = v1;
    }
}

// ===================== small helper kernels =================================
__global__ __launch_bounds__(256) void cvt_bf16(const float* __restrict__ x,
                                                __nv_bfloat16* __restrict__ y)
{
    size_t i = ((size_t)blockIdx.x * 256 + threadIdx.x) * 8;
    float4 a = *(const float4*)(x + i), b = *(const float4*)(x + i + 4);
    __nv_bfloat162 r0 = __floats2bfloat162_rn(a.x, a.y);
    __nv_bfloat162 r1 = __floats2bfloat162_rn(a.z, a.w);
    __nv_bfloat162 r2 = __floats2bfloat162_rn(b.x, b.y);
    __nv_bfloat162 r3 = __floats2bfloat162_rn(b.z, b.w);
    uint4 o;
    o.x = *(uint32_t*)&r0; o.y = *(uint32_t*)&r1;
    o.z = *(uint32_t*)&r2; o.w = *(uint32_t*)&r3;
    *(uint4*)(y + i) = o;
}

// fused weight transposes: z=0 Wq->Wqt, z=1 Wk->Wkvt[0:512], z=2 Wv->Wkvt[512:],
// z=3 Wo->Woth+Wotl
__global__ void tw_fused(const float* __restrict__ Wq, const float* __restrict__ Wk,
                         const float* __restrict__ Wv, const float* __restrict__ Wo,
                         __nv_bfloat16* __restrict__ Wqt, __nv_bfloat16* __restrict__ Wkvt,
                         __nv_bfloat16* __restrict__ Woth, __nv_bfloat16* __restrict__ Wotl)
{
    __shared__ float t[32][33];
    const int zz = blockIdx.z;
    const float* W = (zz == 0) ? Wq : (zz == 1) ? Wk : (zz == 2) ? Wv : Wo;
    __nv_bfloat16* Th = (zz == 0) ? Wqt : (zz == 1) ? Wkvt
                       : (zz == 2) ? (Wkvt + (size_t)512 * DD) : Woth;
    __nv_bfloat16* Tl = (zz == 3) ? Wotl : nullptr;

    const int x = blockIdx.x * 32, y = blockIdx.y * 32;
    const int tx = threadIdx.x, ty = threadIdx.y;
    for (int i = ty; i < 32; i += 8)
        t[i][tx] = W[(size_t)(y + i) * DD + x + tx];
    __syncthreads();
    for (int i = ty; i < 32; i += 8) {
        float v = t[tx][i];
        __nv_bfloat16 hb = __float2bfloat16(v);
        Th[(size_t)(x + i) * DD + y + tx] = hb;
        if (Tl) Tl[(size_t)(x + i) * DD + y + tx] =
            __float2bfloat16(v - __bfloat162float(hb));
    }
}

// residual + layernorm. relu_mode=0: t=X+Y; 1: t=X+relu(Y).
// Optionally also emits hi/lo bf16 split of the result.
__global__ __launch_bounds__(128) void add_ln(
    const float* __restrict__ X, const float* __restrict__ Y,
    const float* __restrict__ g, const float* __restrict__ beta,
    float* __restrict__ out, __nv_bfloat16* __restrict__ ohi,
    __nv_bfloat16* __restrict__ olo, int relu_mode)
{
    const int row = blockIdx.x;
    const int tid = threadIdx.x;
    const size_t base = (size_t)row * DD;
    const int c4 = tid * 4;

    float4 xa = *(const float4*)(X + base + c4);
    float4 ya = *(const float4*)(Y + base + c4);
    float v[4];
    v[0] = relu_mode ? (xa.x + fmaxf(ya.x, 0.f)) : (xa.x + ya.x);
    v[1] = relu_mode ? (xa.y + fmaxf(ya.y, 0.f)) : (xa.y + ya.y);
    v[2] = relu_mode ? (xa.z + fmaxf(ya.z, 0.f)) : (xa.z + ya.z);
    v[3] = relu_mode ? (xa.w + fmaxf(ya.w, 0.f)) : (xa.w + ya.w);
    float s = 0.f, s2 = 0.f;
#pragma unroll
    for (int i = 0; i < 4; i++) { s += v[i]; s2 = fmaf(v[i], v[i], s2); }
#pragma unroll
    for (int o = 16; o > 0; o >>= 1) {
        s  += __shfl_xor_sync(~0u, s, o);
        s2 += __shfl_xor_sync(~0u, s2, o);
    }
    __shared__ float sh[8];
    int w = tid >> 5;
    if ((tid & 31) == 0) { sh[w] = s; sh[4 + w] = s2; }
    __syncthreads();
    if (tid == 0) {
        float S1 = sh[0] + sh[1] + sh[2] + sh[3];
        float S2 = sh[4] + sh[5] + sh[6] + sh[7];
        float mean = S1 * (1.f / DD);
        float var  = S2 * (1.f / DD) - mean * mean;
        sh[0] = mean;
        sh[1] = rsqrtf(var + 1e-5f);
    }
    __syncthreads();
    const float mean = sh[0], rstd = sh[1];
    const float4 gg = *(const float4*)(g + c4);
    const float4 bb = *(const float4*)(beta + c4);
    float4 ov;
    ov.x = (v[0] - mean) * rstd * gg.x + bb.x;
    ov.y = (v[1] - mean) * rstd * gg.y + bb.y;
    ov.z = (v[2] - mean) * rstd * gg.z + bb.z;
    ov.w = (v[3] - mean) * rstd * gg.w + bb.w;
    *(float4*)(out + base + c4) = ov;
    if (ohi) {
        float t[4] = {ov.x, ov.y, ov.z, ov.w};
        __nv_bfloat16 hb[4], lb[4];
#pragma unroll
        for (int i = 0; i < 4; i++) {
            hb[i] = __float2bfloat16(t[i]);
            lb[i] = __float2bfloat16(t[i] - __bfloat162float(hb[i]));
        }
        __nv_bfloat162 h0 = {hb[0], hb[1]}, h1 = {hb[2], hb[3]};
        __nv_bfloat162 l0 = {lb[0], lb[1]}, l1 = {lb[2], lb[3]};
        uint2 ho = {*(uint32_t*)&h0, *(uint32_t*)&h1};
        uint2 lo = {*(uint32_t*)&l0, *(uint32_t*)&l1};
        *(uint2*)(ohi + base + c4) = ho;
        *(uint2*)(olo + base + c4) = lo;
    }
}

// ===================== launch ===============================================
extern "C" void kernel_launch(void* const* d_in, const int* in_sizes, int n_in,
                              void* d_out, int out_size)
{
    const float* Q   = (const float*)d_in[0];
    const float* K   = (const float*)d_in[1];
    const int*   pad = (const int*)  d_in[2];
    const float* Wq  = (const float*)d_in[3];  const float* bq = (const float*)d_in[4];
    const float* Wk  = (const float*)d_in[5];  const float* bk = (const float*)d_in[6];
    const float* Wv  = (const float*)d_in[7];  const float* bv = (const float*)d_in[8];
    const float* Wo  = (const float*)d_in[9];  const float* bo = (const float*)d_in[10];
    const float* g0  = (const float*)d_in[11]; const float* b0 = (const float*)d_in[12];
    const float* g1  = (const float*)d_in[13]; const float* b1 = (const float*)d_in[14];
    float* out = (float*)d_out;

    __nv_bfloat16 *Qb, *Kb, *Qh, *KVh, *x1h, *x1l, *Wqt, *Wkvt, *Woth, *Wotl;
    float *attn, *x1, *y;
    cudaGetSymbolAddress((void**)&Qb,   g_Qb);   cudaGetSymbolAddress((void**)&Kb,   g_Kb);
    cudaGetSymbolAddress((void**)&Qh,   g_Qh);   cudaGetSymbolAddress((void**)&KVh,  g_KVh);
    cudaGetSymbolAddress((void**)&attn, g_attn); cudaGetSymbolAddress((void**)&x1,   g_x1);
    cudaGetSymbolAddress((void**)&x1h,  g_x1h);  cudaGetSymbolAddress((void**)&x1l,  g_x1l);
    cudaGetSymbolAddress((void**)&y,    g_y);
    cudaGetSymbolAddress((void**)&Wqt,  g_Wqt);  cudaGetSymbolAddress((void**)&Wkvt, g_Wkvt);
    cudaGetSymbolAddress((void**)&Woth, g_Woth); cudaGetSymbolAddress((void**)&Wotl, g_Wotl);

    const int smem_g1 = 4 * 1 * (128 + 128) * 40 * 2;   // 81920 (4-stage)
    const int smem_g3 = 2 * 2 * (128 + 128) * 40 * 2;   // 81920 (2-stage, TERMS=3)
    const int smem_fl = (FBQ * FLDS + 4 * FSK * FLDS) * 2 + 2 * FSK * 4;  // 93184
    cudaFuncSetAttribute((const void*)mma_gemm<128, 1, true,  true,  4>,
                         cudaFuncAttributeMaxDynamicSharedMemorySize, smem_g1);
    cudaFuncSetAttribute((const void*)mma_gemm<128, 3, false, true,  2>,
                         cudaFuncAttributeMaxDynamicSharedMemorySize, smem_g3);
    cudaFuncSetAttribute((const void*)flash_mma,
                         cudaFuncAttributeMaxDynamicSharedMemorySize, smem_fl);

    // 1/sqrt(512) * log2(e): scores land in log2 domain for ex2-based softmax
    const float qscale = 0.04419417382415922f * 1.4426950408889634f;

    // launches 0,1: input conversions
    cvt_bf16<<<(MROWS * DD) / (256 * 8), 256>>>(Q, Qb);
    cvt_bf16<<<(MROWS * DD) / (256 * 8), 256>>>(K, Kb);
    // launch 2: all weight transposes
    tw_fused<<<dim3(16, 16, 4), dim3(32, 8)>>>(Wq, Wk, Wv, Wo, Wqt, Wkvt, Woth, Wotl);

    // launch 3: Q projection (pre-scaled)
    dim3 pgq(DD / 128, MROWS / 128);
    mma_gemm<128, 1, true, true, 4><<<pgq, 256, smem_g1>>>(
        Qb, nullptr, DD, Wqt, nullptr, DD, Qh, DD, bq, nullptr, qscale, DD);
    // launch 4: fused K+V projection into packed KV (N = 1024)
    dim3 pgkv(KVLD / 128, MROWS / 128);
    mma_gemm<128, 1, true, true, 4><<<pgkv, 256, smem_g1>>>(
        Kb, nullptr, DD, Wkvt, nullptr, DD, KVh, KVLD, bk, bv, 1.0f, DD);

    // launch 5: fused attention  (ncu -s 5 -c 1 profiles this one)
    flash_mma<<<dim3(LQ / FBQ, BHN), 256, smem_fl>>>(Qh, KVh, pad, attn);

    // launch 6: residual + LN (+ hi/lo split of x1)
    add_ln<<<MROWS, 128>>>(Q, attn, g0, b0, x1, x1h, x1l, 0);

    // launch 7: Wo GEMM, 3-term bf16 hi/lo split
    mma_gemm<128, 3, false, true, 2><<<pgq, 256, smem_g3>>>(
        x1h, x1l, DD, Woth, Wotl, DD, y, DD, bo, nullptr, 1.0f, DD);

    // launch 8: final residual + LN
    add_ln<<<MROWS, 128>>>(x1, y, g1, b1, out, nullptr, nullptr, 1);
}

// round 8
// speedup vs baseline: 6.2755x; 1.1883x over previous
#include <cuda_runtime.h>
#include <cuda_bf16.h>
#include <cuda_fp16.h>
#include <cstdint>
#include <math.h>

#define BB 4
#define LQ 2048
#define LK 2048
#define DD 512
#define HH 8
#define DH 64
#define MROWS (BB * LQ)            // 8192
#define BHN  (BB * HH)             // 32
#define KVLD 1024                  // packed KV row stride (K cols 0-511, V cols 512-1023)

// ===================== scratch (static device globals) ======================
__device__ __nv_bfloat16 g_Qb [(size_t)MROWS * DD];
__device__ __nv_bfloat16 g_Kb [(size_t)MROWS * DD];
__device__ __half        g_Qh [(size_t)MROWS * DD];
__device__ __half        g_KVh[(size_t)MROWS * KVLD];
__device__ float         g_attn[(size_t)MROWS * DD];
__device__ float         g_x1 [(size_t)MROWS * DD];
__device__ __nv_bfloat16 g_x1h[(size_t)MROWS * DD];
__device__ __nv_bfloat16 g_x1l[(size_t)MROWS * DD];
__device__ float         g_y  [(size_t)MROWS * DD];
__device__ __nv_bfloat16 g_Wqt [(size_t)DD * DD];
__device__ __nv_bfloat16 g_Wkvt[(size_t)2 * DD * DD];   // rows 0-511: Wk^T, 512-1023: Wv^T
__device__ __nv_bfloat16 g_Woth[(size_t)DD * DD];
__device__ __nv_bfloat16 g_Wotl[(size_t)DD * DD];

// ===================== low-level helpers (sm_80+ only) ======================
__device__ __forceinline__ uint32_t smem_u32(const void* p) {
    uint32_t a;
    asm("{ .reg .u64 t; cvta.to.shared.u64 t, %1; cvt.u32.u64 %0, t; }"
        : "=r"(a) : "l"(p));
    return a;
}
__device__ __forceinline__ void cp_async16(uint32_t dst, const void* src) {
    asm volatile("cp.async.cg.shared.global [%0], [%1], 16;"
                 :: "r"(dst), "l"(src) : "memory");
}
#define CP_COMMIT() asm volatile("cp.async.commit_group;" ::: "memory")

__device__ __forceinline__ void ldm_x4(uint32_t* r, uint32_t addr) {
    asm volatile("ldmatrix.sync.aligned.m8n8.x4.shared.b16 {%0,%1,%2,%3}, [%4];"
                 : "=r"(r[0]), "=r"(r[1]), "=r"(r[2]), "=r"(r[3]) : "r"(addr));
}
__device__ __forceinline__ void ldm_x4_t(uint32_t* r, uint32_t addr) {
    asm volatile("ldmatrix.sync.aligned.m8n8.x4.trans.shared.b16 {%0,%1,%2,%3}, [%4];"
                 : "=r"(r[0]), "=r"(r[1]), "=r"(r[2]), "=r"(r[3]) : "r"(addr));
}
__device__ __forceinline__ void ldm_x2(uint32_t* r, uint32_t addr) {
    asm volatile("ldmatrix.sync.aligned.m8n8.x2.shared.b16 {%0,%1}, [%2];"
                 : "=r"(r[0]), "=r"(r[1]) : "r"(addr));
}
__device__ __forceinline__ void mma_bf16(float* d, const uint32_t* a, const uint32_t* b) {
    asm volatile(
        "mma.sync.aligned.m16n8k16.row.col.f32.bf16.bf16.f32 "
        "{%0,%1,%2,%3}, {%4,%5,%6,%7}, {%8,%9}, {%0,%1,%2,%3};"
        : "+f"(d[0]), "+f"(d[1]), "+f"(d[2]), "+f"(d[3])
        : "r"(a[0]), "r"(a[1]), "r"(a[2]), "r"(a[3]), "r"(b[0]), "r"(b[1]));
}
__device__ __forceinline__ void mma_f16(float* d, const uint32_t* a, const uint32_t* b) {
    asm volatile(
        "mma.sync.aligned.m16n8k16.row.col.f32.f16.f16.f32 "
        "{%0,%1,%2,%3}, {%4,%5,%6,%7}, {%8,%9}, {%0,%1,%2,%3};"
        : "+f"(d[0]), "+f"(d[1]), "+f"(d[2]), "+f"(d[3])
        : "r"(a[0]), "r"(a[1]), "r"(a[2]), "r"(a[3]), "r"(b[0]), "r"(b[1]));
}
__device__ __forceinline__ float fexp2(float x) {
    float y;
    asm("ex2.approx.f32 %0, %1;" : "=f"(y) : "f"(x));
    return y;
}
// pack (lo, hi) -> f16x2, then elementwise exp2. Result IS a P-fragment register.
__device__ __forceinline__ uint32_t pexp2(float lo, float hi) {
    uint32_t h, r;
    asm("cvt.rn.f16x2.f32 %0, %1, %2;" : "=r"(h) : "f"(hi), "f"(lo));
    asm("ex2.approx.f16x2 %0, %1;" : "=r"(r) : "r"(h));
    return r;
}

// ===================== generic warp-MMA GEMM ================================
// D[128, BN-tile of N] = sum_K A[128,K] * B[N,K]^T  (bf16 in, fp32 accum)
// TERMS==3: A = Ahi+Alo, B = Bhi+Blo; computes hi*hi + hi*lo + lo*hi.
// OUTT: 0 = fp32, 1 = bf16, 2 = fp16 output.
// NS==4: single-barrier-per-k-step schedule (stage (kt+2)%4 last read at
// compute(kt-2), finished before barrier of iteration kt-1 -> safe).
template<int BN, int TERMS, int OUTT, bool HAS_BIAS, int NS>
__global__ __launch_bounds__(256)
void mma_gemm(const __nv_bfloat16* __restrict__ A,  const __nv_bfloat16* __restrict__ Alo,
              long long lda,
              const __nv_bfloat16* __restrict__ Bm, const __nv_bfloat16* __restrict__ Blo,
              long long ldb,
              void* __restrict__ Cout, long long ldc,
              const float* __restrict__ bias, const float* __restrict__ bias2,
              float outScale, int Ksz)
{
    constexpr int NTm   = (TERMS == 3) ? 2 : 1;
    constexpr int LDS   = 40;                  // padded row (elements): 80B stride
    constexpr int A_ELE = 128 * LDS;
    constexpr int B_ELE = BN * LDS;
    constexpr int STAGE = NTm * (A_ELE + B_ELE);
    constexpr int WN    = BN / 4;
    constexpr int NT_   = WN / 8;

    extern __shared__ __align__(16) __nv_bfloat16 sm_[];
    const int tid = threadIdx.x, wid = tid >> 5, lane = tid & 31;
    const int warp_m = wid & 1, warp_n = wid >> 1;
    const int m0 = blockIdx.y * 128, n0b = blockIdx.x * BN;

    const __nv_bfloat16* Ab  = A  + (long long)m0  * lda;
    const __nv_bfloat16* Bb  = Bm + (long long)n0b * ldb;
    const __nv_bfloat16* Abl = (TERMS == 3) ? (Alo + (long long)m0  * lda) : nullptr;
    const __nv_bfloat16* Bbl = (TERMS == 3) ? (Blo + (long long)n0b * ldb) : nullptr;

    const uint32_t sbase = smem_u32(sm_);

    float acc[4][NT_][4];
#pragma unroll
    for (int i = 0; i < 4; i++)
#pragma unroll
        for (int j = 0; j < NT_; j++)
#pragma unroll
            for (int k = 0; k < 4; k++) acc[i][j][k] = 0.f;

    auto load_stage = [&](int kt, int s) {
        const int koff = kt * 32;
        const uint32_t stA = sbase + (uint32_t)(s * STAGE) * 2;
        const uint32_t stB = stA + (uint32_t)(NTm * A_ELE) * 2;
#pragma unroll
        for (int i = tid; i < 512; i += 256) {
            int r = i >> 2, c = i & 3;
            cp_async16(stA + (uint32_t)(r * LDS + c * 8) * 2,
                       Ab + (long long)r * lda + koff + c * 8);
        }
        if (TERMS == 3) {
#pragma unroll
            for (int i = tid; i < 512; i += 256) {
                int r = i >> 2, c = i & 3;
                cp_async16(stA + (uint32_t)(A_ELE + r * LDS + c * 8) * 2,
                           Abl + (long long)r * lda + koff + c * 8);
            }
        }
#pragma unroll
        for (int i = tid; i < BN * 4; i += 256) {
            int r = i >> 2, c = i & 3;
            cp_async16(stB + (uint32_t)(r * LDS + c * 8) * 2,
                       Bb + (long long)r * ldb + koff + c * 8);
        }
        if (TERMS == 3) {
#pragma unroll
            for (int i = tid; i < BN * 4; i += 256) {
                int r = i >> 2, c = i & 3;
                cp_async16(stB + (uint32_t)(B_ELE + r * LDS + c * 8) * 2,
                           Bbl + (long long)r * ldb + koff + c * 8);
            }
        }
        CP_COMMIT();
    };

    auto compute_stage = [&](int s) {
        const uint32_t aBase0 = sbase + (uint32_t)(s * STAGE) * 2;
        const uint32_t bBase0 = aBase0 + (uint32_t)(NTm * A_ELE) * 2;
#pragma unroll
        for (int t = 0; t < TERMS; t++) {
            const uint32_t aB = aBase0 + ((t == 2) ? (uint32_t)A_ELE * 2 : 0u);
            const uint32_t bB = bBase0 + ((t == 1) ? (uint32_t)B_ELE * 2 : 0u);
#pragma unroll
            for (int ks = 0; ks < 2; ks++) {
                uint32_t af[4][4], bf[NT_][2];
#pragma unroll
                for (int mt = 0; mt < 4; mt++) {
                    uint32_t addr = aB + (uint32_t)(
                        (warp_m * 64 + mt * 16 + (lane & 15)) * LDS
                        + ks * 16 + ((lane >> 4) << 3)) * 2;
                    ldm_x4(af[mt], addr);
                }
#pragma unroll
                for (int nt = 0; nt < NT_; nt++) {
                    uint32_t addr = bB + (uint32_t)(
                        (warp_n * WN + nt * 8 + (lane & 7)) * LDS
                        + ks * 16 + (((lane >> 3) & 1) << 3)) * 2;
                    ldm_x2(bf[nt], addr);
                }
#pragma unroll
                for (int mt = 0; mt < 4; mt++)
#pragma unroll
                    for (int nt = 0; nt < NT_; nt++)
                        mma_bf16(acc[mt][nt], af[mt], bf[nt]);
            }
        }
    };

    const int KT = Ksz >> 5;
    if (NS == 4) {
        load_stage(0, 0);
        if (KT > 1) load_stage(1, 1);
        for (int kt = 0; kt < KT; kt++) {
            if (kt + 2 < KT) {
                load_stage(kt + 2, (kt + 2) & 3);
                asm volatile("cp.async.wait_group 2;" ::: "memory");
            } else if (kt + 1 < KT) {
                asm volatile("cp.async.wait_group 1;" ::: "memory");
            } else {
                asm volatile("cp.async.wait_group 0;" ::: "memory");
            }
            __syncthreads();
            compute_stage(kt & 3);
        }
    } else {
        load_stage(0, 0);
        for (int kt = 0; kt < KT; kt++) {
            if (kt + 1 < KT) {
                load_stage(kt + 1, (kt + 1) & 1);
                asm volatile("cp.async.wait_group 1;" ::: "memory");
            } else {
                asm volatile("cp.async.wait_group 0;" ::: "memory");
            }
            __syncthreads();
            compute_stage(kt & 1);
            __syncthreads();
        }
    }

    // epilogue
#pragma unroll
    for (int mt = 0; mt < 4; mt++) {
        const int rb = m0 + warp_m * 64 + mt * 16 + (lane >> 2);
#pragma unroll
        for (int nt = 0; nt < NT_; nt++) {
            const int c0 = n0b + warp_n * WN + nt * 8 + (lane & 3) * 2;
            float bx = 0.f, by = 0.f;
            if (HAS_BIAS) {
                if (bias2 && c0 >= 512) { bx = bias2[c0 - 512]; by = bias2[c0 - 511]; }
                else                    { bx = bias[c0];        by = bias[c0 + 1];    }
            }
#pragma unroll
            for (int half = 0; half < 2; half++) {
                const int r = rb + half * 8;
                float x0 = (acc[mt][nt][half * 2 + 0] + bx) * outScale;
                float x1 = (acc[mt][nt][half * 2 + 1] + by) * outScale;
                if (OUTT == 1) {
                    __nv_bfloat16* C = (__nv_bfloat16*)Cout + (long long)r * ldc + c0;
                    *(__nv_bfloat162*)C = __floats2bfloat162_rn(x0, x1);
                } else if (OUTT == 2) {
                    __half* C = (__half*)Cout + (long long)r * ldc + c0;
                    *(__half2*)C = __floats2half2_rn(x0, x1);
                } else {
                    float* C = (float*)Cout + (long long)r * ldc + c0;
                    float2 v; v.x = x0; v.y = x1;
                    *(float2*)C = v;
                }
            }
        }
    }
}

// ===================== fused flash attention (fp16 mma.sync) ================
// Grid: (LQ/128, BHN). 256 threads = 8 warps; warp w owns rows 16w..16w+15.
// K/V in 128-key double-buffered stages, two 64-key compute subtiles each.
// Scores pre-scaled by log2e; P = ex2.approx.f16x2 of (s - m) pairs; masked
// keys get a -1e30 score bias (cvt -> -inf -> exp -> exact 0).
// l is accumulated by an extra P @ ones MMA column, rescaled like O, so the
// final normalizer is exactly consistent with the PV sum.
#define FBQ 128
#define FSK 128      // keys per load stage
#define FLDS 72      // padded row: 144 B stride -> ldmatrix conflict-free

__global__ __launch_bounds__(256, 2)
void flash_mma(const __half* __restrict__ Qh,
               const __half* __restrict__ KVh,
               const int* __restrict__ pad,
               float* __restrict__ Out)
{
    extern __shared__ __align__(16) char fsm[];
    __half* Qs = (__half*)fsm;                  // 128*72
    __half* Ks = Qs + FBQ * FLDS;               // 2 * 128*72
    __half* Vs = Ks + 2 * FSK * FLDS;           // 2 * 128*72
    int*    Ms = (int*)(Vs + 2 * FSK * FLDS);   // 2 * 128

    const int tid = threadIdx.x, wid = tid >> 5, lane = tid & 31;
    const int q0 = blockIdx.x * FBQ;
    const int z = blockIdx.y, b = z >> 3, h = z & 7;
    const uint32_t sQ = smem_u32(Qs), sK = smem_u32(Ks);
    const uint32_t sV = smem_u32(Vs), sM = smem_u32(Ms);

    const __half* Qp = Qh + ((size_t)(b * LQ + q0)) * DD + h * DH;
    const __half* Kp = KVh + ((size_t)b * LK) * KVLD + h * DH;        // K cols
    const __half* Vp = KVh + ((size_t)b * LK) * KVLD + 512 + h * DH;  // V cols
    const int* pp = pad + b * LK;

    // Q tile -> smem
#pragma unroll
    for (int i = tid; i < 1024; i += 256) {
        int r = i >> 3, c = i & 7;
        cp_async16(sQ + (uint32_t)(r * FLDS + c * 8) * 2, Qp + (size_t)r * DD + c * 8);
    }
    CP_COMMIT();

    auto load_kv = [&](int st, int s) {
        const int k0 = st * FSK;
        const uint32_t kb = sK + (uint32_t)(s * FSK * FLDS) * 2;
        const uint32_t vb = sV + (uint32_t)(s * FSK * FLDS) * 2;
#pragma unroll
        for (int i = tid; i < 1024; i += 256) {
            int r = i >> 3, c = i & 7;
            cp_async16(kb + (uint32_t)(r * FLDS + c * 8) * 2,
                       Kp + (size_t)(k0 + r) * KVLD + c * 8);
            cp_async16(vb + (uint32_t)(r * FLDS + c * 8) * 2,
                       Vp + (size_t)(k0 + r) * KVLD + c * 8);
        }
        if (tid < 32)
            cp_async16(sM + (uint32_t)(s * FSK + tid * 4) * 4, pp + k0 + tid * 4);
        CP_COMMIT();
    };

    load_kv(0, 0);

    const uint32_t bones[2] = {0x3C003C00u, 0x3C003C00u};   // f16 ones fragment
    uint32_t qf[4][4];
    float o[8][4];
    float losum[4] = {0.f, 0.f, 0.f, 0.f};
#pragma unroll
    for (int i = 0; i < 8; i++)
#pragma unroll
        for (int j = 0; j < 4; j++) o[i][j] = 0.f;
    float m0 = -1e30f, m1 = -1e30f;

    const int NST = LK / FSK;   // 16
    for (int st = 0; st < NST; st++) {
        const int s = st & 1;
        if (st + 1 < NST) {
            load_kv(st + 1, s ^ 1);
            asm volatile("cp.async.wait_group 1;" ::: "memory");
        } else {
            asm volatile("cp.async.wait_group 0;" ::: "memory");
        }
        __syncthreads();
        if (st == 0) {
#pragma unroll
            for (int ks = 0; ks < 4; ks++) {
                uint32_t addr = sQ + (uint32_t)(
                    (wid * 16 + (lane & 15)) * FLDS + ks * 16 + ((lane >> 4) << 3)) * 2;
                ldm_x4(qf[ks], addr);
            }
        }

#pragma unroll
        for (int hk = 0; hk < 2; hk++) {
            const uint32_t kb = sK + (uint32_t)((s * FSK + hk * 64) * FLDS) * 2;
            const uint32_t vb = sV + (uint32_t)((s * FSK + hk * 64) * FLDS) * 2;
            const int* mskp = Ms + s * FSK + hk * 64;

            // ---- S = Q K^T (log2-domain scores) ----
            float sa[8][4];
#pragma unroll
            for (int i = 0; i < 8; i++)
#pragma unroll
                for (int j = 0; j < 4; j++) sa[i][j] = 0.f;
#pragma unroll
            for (int ks = 0; ks < 4; ks++) {
                uint32_t bk[8][2];
#pragma unroll
                for (int np = 0; np < 4; np++) {
                    uint32_t r4[4];
                    uint32_t addr = kb + (uint32_t)(
                        (np * 16 + (lane & 15)) * FLDS + ks * 16 + ((lane >> 4) << 3)) * 2;
                    ldm_x4(r4, addr);
                    bk[2 * np][0] = r4[0]; bk[2 * np][1] = r4[2];
                    bk[2 * np + 1][0] = r4[1]; bk[2 * np + 1][1] = r4[3];
                }
#pragma unroll
                for (int nt = 0; nt < 8; nt++) mma_f16(sa[nt], qf[ks], bk[nt]);
            }

            // ---- mask via score bias, then plain max ----
            const int cb = (lane & 3) * 2;
#pragma unroll
            for (int nt = 0; nt < 8; nt++) {
                const float b0 = mskp[nt * 8 + cb]     ? 0.f : -1e30f;
                const float b1 = mskp[nt * 8 + cb + 1] ? 0.f : -1e30f;
                sa[nt][0] += b0; sa[nt][1] += b1;
                sa[nt][2] += b0; sa[nt][3] += b1;
            }
            float mx0 = sa[0][0], mx1 = sa[0][2];
#pragma unroll
            for (int nt = 0; nt < 8; nt++) {
                mx0 = fmaxf(mx0, fmaxf(sa[nt][0], sa[nt][1]));
                mx1 = fmaxf(mx1, fmaxf(sa[nt][2], sa[nt][3]));
            }
            mx0 = fmaxf(mx0, __shfl_xor_sync(~0u, mx0, 1));
            mx0 = fmaxf(mx0, __shfl_xor_sync(~0u, mx0, 2));
            mx1 = fmaxf(mx1, __shfl_xor_sync(~0u, mx1, 1));
            mx1 = fmaxf(mx1, __shfl_xor_sync(~0u, mx1, 2));
            const float mn0 = fmaxf(m0, mx0), mn1 = fmaxf(m1, mx1);
            const float al0 = fexp2(m0 - mn0), al1 = fexp2(m1 - mn1);
            m0 = mn0; m1 = mn1;

            // ---- P fragments: packed f16x2 exp2 of (s - m) ----
            uint32_t pf[4][4];
#pragma unroll
            for (int ks = 0; ks < 4; ks++) {
                pf[ks][0] = pexp2(sa[2 * ks][0] - mn0,     sa[2 * ks][1] - mn0);
                pf[ks][1] = pexp2(sa[2 * ks][2] - mn1,     sa[2 * ks][3] - mn1);
                pf[ks][2] = pexp2(sa[2 * ks + 1][0] - mn0, sa[2 * ks + 1][1] - mn0);
                pf[ks][3] = pexp2(sa[2 * ks + 1][2] - mn1, sa[2 * ks + 1][3] - mn1);
            }

            // ---- rescale O and l-accumulator ----
#pragma unroll
            for (int nt = 0; nt < 8; nt++) {
                o[nt][0] *= al0; o[nt][1] *= al0;
                o[nt][2] *= al1; o[nt][3] *= al1;
            }
            losum[0] *= al0; losum[1] *= al0;
            losum[2] *= al1; losum[3] *= al1;

            // ---- O += P V; l += P @ ones ----
#pragma unroll
            for (int ks = 0; ks < 4; ks++) {
                mma_f16(losum, pf[ks], bones);
#pragma unroll
                for (int np = 0; np < 4; np++) {
                    uint32_t r4[4];
                    uint32_t addr = vb + (uint32_t)(
                        (ks * 16 + (lane & 15)) * FLDS + np * 16 + ((lane >> 4) << 3)) * 2;
                    ldm_x4_t(r4, addr);
                    mma_f16(o[2 * np],     pf[ks], r4);
                    mma_f16(o[2 * np + 1], pf[ks], r4 + 2);
                }
            }
        }
        __syncthreads();
    }

    // ---- write O (losum[0]/losum[2] hold the exact row sums) ----
    const float l0 = losum[0], l1 = losum[2];
    const float inv0 = (l0 > 0.f) ? 1.f / l0 : 0.f;
    const float inv1 = (l1 > 0.f) ? 1.f / l1 : 0.f;
    const int r0g = q0 + wid * 16 + (lane >> 2);
    float* ob0 = Out + ((size_t)(b * LQ + r0g)) * DD + h * DH + (lane & 3) * 2;
    float* ob1 = ob0 + (size_t)8 * DD;
#pragma unroll
    for (int nt = 0; nt < 8; nt++) {
        float2 v0; v0.x = o[nt][0] * inv0; v0.y = o[nt][1] * inv0;
        float2 v1; v1.x = o[nt][2] * inv1; v1.y = o[nt][3] * inv1;
        *(float2*)(ob0 + nt * 8) = v0;
        *(float2*)(ob1 + nt * 8) = v1;
    }
}

// ===================== small helper kernels =================================
// grid.y selects source: 0 -> (Q -> Qb), 1 -> (K -> Kb)
__global__ __launch_bounds__(256) void cvt_bf16_dual(
    const float* __restrict__ Qs, const float* __restrict__ Ksrc,
    __nv_bfloat16* __restrict__ Qd, __nv_bfloat16* __restrict__ Kd)
{
    const float* x = blockIdx.y ? Ksrc : Qs;
    __nv_bfloat16* y = blockIdx.y ? Kd : Qd;
    size_t i = ((size_t)blockIdx.x * 256 + threadIdx.x) * 8;
    float4 a = *(const float4*)(x + i), b = *(const float4*)(x + i + 4);
    __nv_bfloat162 r0 = __floats2bfloat162_rn(a.x, a.y);
    __nv_bfloat162 r1 = __floats2bfloat162_rn(a.z, a.w);
    __nv_bfloat162 r2 = __floats2bfloat162_rn(b.x, b.y);
    __nv_bfloat162 r3 = __floats2bfloat162_rn(b.z, b.w);
    uint4 o;
    o.x = *(uint32_t*)&r0; o.y = *(uint32_t*)&r1;
    o.z = *(uint32_t*)&r2; o.w = *(uint32_t*)&r3;
    *(uint4*)(y + i) = o;
}

// fused weight transposes: z=0 Wq->Wqt, z=1 Wk->Wkvt[0:512], z=2 Wv->Wkvt[512:],
// z=3 Wo->Woth+Wotl
__global__ void tw_fused(const float* __restrict__ Wq, const float* __restrict__ Wk,
                         const float* __restrict__ Wv, const float* __restrict__ Wo,
                         __nv_bfloat16* __restrict__ Wqt, __nv_bfloat16* __restrict__ Wkvt,
                         __nv_bfloat16* __restrict__ Woth, __nv_bfloat16* __restrict__ Wotl)
{
    __shared__ float t[32][33];
    const int zz = blockIdx.z;
    const float* W = (zz == 0) ? Wq : (zz == 1) ? Wk : (zz == 2) ? Wv : Wo;
    __nv_bfloat16* Th = (zz == 0) ? Wqt : (zz == 1) ? Wkvt
                       : (zz == 2) ? (Wkvt + (size_t)512 * DD) : Woth;
    __nv_bfloat16* Tl = (zz == 3) ? Wotl : nullptr;

    const int x = blockIdx.x * 32, y = blockIdx.y * 32;
    const int tx = threadIdx.x, ty = threadIdx.y;
    for (int i = ty; i < 32; i += 8)
        t[i][tx] = W[(size_t)(y + i) * DD + x + tx];
    __syncthreads();
    for (int i = ty; i < 32; i += 8) {
        float v = t[tx][i];
        __nv_bfloat16 hb = __float2bfloat16(v);
        Th[(size_t)(x + i) * DD + y + tx] = hb;
        if (Tl) Tl[(size_t)(x + i) * DD + y + tx] =
            __float2bfloat16(v - __bfloat162float(hb));
    }
}

// residual + layernorm. relu_mode=0: t=X+Y; 1: t=X+relu(Y).
// Optionally also emits hi/lo bf16 split of the result.
__global__ __launch_bounds__(128) void add_ln(
    const float* __restrict__ X, const float* __restrict__ Y,
    const float* __restrict__ g, const float* __restrict__ beta,
    float* __restrict__ out, __nv_bfloat16* __restrict__ ohi,
    __nv_bfloat16* __restrict__ olo, int relu_mode)
{
    const int row = blockIdx.x;
    const int tid = threadIdx.x;
    const size_t base = (size_t)row * DD;
    const int c4 = tid * 4;

    float4 xa = *(const float4*)(X + base + c4);
    float4 ya = *(const float4*)(Y + base + c4);
    float v[4];
    v[0] = relu_mode ? (xa.x + fmaxf(ya.x, 0.f)) : (xa.x + ya.x);
    v[1] = relu_mode ? (xa.y + fmaxf(ya.y, 0.f)) : (xa.y + ya.y);
    v[2] = relu_mode ? (xa.z + fmaxf(ya.z, 0.f)) : (xa.z + ya.z);
    v[3] = relu_mode ? (xa.w + fmaxf(ya.w, 0.f)) : (xa.w + ya.w);
    float s = 0.f, s2 = 0.f;
#pragma unroll
    for (int i = 0; i < 4; i++) { s += v[i]; s2 = fmaf(v[i], v[i], s2); }
#pragma unroll
    for (int o = 16; o > 0; o >>= 1) {
        s  += __shfl_xor_sync(~0u, s, o);
        s2 += __shfl_xor_sync(~0u, s2, o);
    }
    __shared__ float sh[8];
    int w = tid >> 5;
    if ((tid & 31) == 0) { sh[w] = s; sh[4 + w] = s2; }
    __syncthreads();
    if (tid == 0) {
        float S1 = sh[0] + sh[1] + sh[2] + sh[3];
        float S2 = sh[4] + sh[5] + sh[6] + sh[7];
        float mean = S1 * (1.f / DD);
        float var  = S2 * (1.f / DD) - mean * mean;
        sh[0] = mean;
        sh[1] = rsqrtf(var + 1e-5f);
    }
    __syncthreads();
    const float mean = sh[0], rstd = sh[1];
    const float4 gg = *(const float4*)(g + c4);
    const float4 bb = *(const float4*)(beta + c4);
    float4 ov;
    ov.x = (v[0] - mean) * rstd * gg.x + bb.x;
    ov.y = (v[1] - mean) * rstd * gg.y + bb.y;
    ov.z = (v[2] - mean) * rstd * gg.z + bb.z;
    ov.w = (v[3] - mean) * rstd * gg.w + bb.w;
    *(float4*)(out + base + c4) = ov;
    if (ohi) {
        float t[4] = {ov.x, ov.y, ov.z, ov.w};
        __nv_bfloat16 hb[4], lb[4];
#pragma unroll
        for (int i = 0; i < 4; i++) {
            hb[i] = __float2bfloat16(t[i]);
            lb[i] = __float2bfloat16(t[i] - __bfloat162float(hb[i]));
        }
        __nv_bfloat162 h0 = {hb[0], hb[1]}, h1 = {hb[2], hb[3]};
        __nv_bfloat162 l0 = {lb[0], lb[1]}, l1 = {lb[2], lb[3]};
        uint2 ho = {*(uint32_t*)&h0, *(uint32_t*)&h1};
        uint2 lo = {*(uint32_t*)&l0, *(uint32_t*)&l1};
        *(uint2*)(ohi + base + c4) = ho;
        *(uint2*)(olo + base + c4) = lo;
    }
}

// ===================== launch ===============================================
extern "C" void kernel_launch(void* const* d_in, const int* in_sizes, int n_in,
                              void* d_out, int out_size)
{
    const float* Q   = (const float*)d_in[0];
    const float* K   = (const float*)d_in[1];
    const int*   pad = (const int*)  d_in[2];
    const float* Wq  = (const float*)d_in[3];  const float* bq = (const float*)d_in[4];
    const float* Wk  = (const float*)d_in[5];  const float* bk = (const float*)d_in[6];
    const float* Wv  = (const float*)d_in[7];  const float* bv = (const float*)d_in[8];
    const float* Wo  = (const float*)d_in[9];  const float* bo = (const float*)d_in[10];
    const float* g0  = (const float*)d_in[11]; const float* b0 = (const float*)d_in[12];
    const float* g1  = (const float*)d_in[13]; const float* b1 = (const float*)d_in[14];
    float* out = (float*)d_out;

    __nv_bfloat16 *Qb, *Kb, *x1h, *x1l, *Wqt, *Wkvt, *Woth, *Wotl;
    __half *Qh, *KVh;
    float *attn, *x1, *y;
    cudaGetSymbolAddress((void**)&Qb,   g_Qb);   cudaGetSymbolAddress((void**)&Kb,   g_Kb);
    cudaGetSymbolAddress((void**)&Qh,   g_Qh);   cudaGetSymbolAddress((void**)&KVh,  g_KVh);
    cudaGetSymbolAddress((void**)&attn, g_attn); cudaGetSymbolAddress((void**)&x1,   g_x1);
    cudaGetSymbolAddress((void**)&x1h,  g_x1h);  cudaGetSymbolAddress((void**)&x1l,  g_x1l);
    cudaGetSymbolAddress((void**)&y,    g_y);
    cudaGetSymbolAddress((void**)&Wqt,  g_Wqt);  cudaGetSymbolAddress((void**)&Wkvt, g_Wkvt);
    cudaGetSymbolAddress((void**)&Woth, g_Woth); cudaGetSymbolAddress((void**)&Wotl, g_Wotl);

    const int smem_g1 = 4 * 1 * (128 + 128) * 40 * 2;   // 81920 (4-stage)
    const int smem_g3 = 2 * 2 * (128 + 128) * 40 * 2;   // 81920 (2-stage, TERMS=3)
    const int smem_fl = (FBQ * FLDS + 4 * FSK * FLDS) * 2 + 2 * FSK * 4;  // 93184
    cudaFuncSetAttribute((const void*)mma_gemm<128, 1, 2, true, 4>,
                         cudaFuncAttributeMaxDynamicSharedMemorySize, smem_g1);
    cudaFuncSetAttribute((const void*)mma_gemm<128, 3, 0, true, 2>,
                         cudaFuncAttributeMaxDynamicSharedMemorySize, smem_g3);
    cudaFuncSetAttribute((const void*)flash_mma,
                         cudaFuncAttributeMaxDynamicSharedMemorySize, smem_fl);

    // 1/sqrt(512) * log2(e): scores land in log2 domain for ex2-based softmax
    const float qscale = 0.04419417382415922f * 1.4426950408889634f;

    // launch 0: input conversions (Q and K in one launch)
    cvt_bf16_dual<<<dim3((MROWS * DD) / (256 * 8), 2), 256>>>(Q, K, Qb, Kb);
    // launch 1: all weight transposes
    tw_fused<<<dim3(16, 16, 4), dim3(32, 8)>>>(Wq, Wk, Wv, Wo, Wqt, Wkvt, Woth, Wotl);

    // launch 2: Q projection (pre-scaled, fp16 out)
    dim3 pgq(DD / 128, MROWS / 128);
    mma_gemm<128, 1, 2, true, 4><<<pgq, 256, smem_g1>>>(
        Qb, nullptr, DD, Wqt, nullptr, DD, Qh, DD, bq, nullptr, qscale, DD);
    // launch 3: fused K+V projection into packed KV (N = 1024, fp16 out)
    dim3 pgkv(KVLD / 128, MROWS / 128);
    mma_gemm<128, 1, 2, true, 4><<<pgkv, 256, smem_g1>>>(
        Kb, nullptr, DD, Wkvt, nullptr, DD, KVh, KVLD, bk, bv, 1.0f, DD);

    // launch 4: fused attention (profiled slot)
    flash_mma<<<dim3(LQ / FBQ, BHN), 256, smem_fl>>>(Qh, KVh, pad, attn);

    // launch 5: residual + LN (+ hi/lo split of x1)
    add_ln<<<MROWS, 128>>>(Q, attn, g0, b0, x1, x1h, x1l, 0);

    // launch 6: Wo GEMM, 3-term bf16 hi/lo split
    mma_gemm<128, 3, 0, true, 2><<<pgq, 256, smem_g3>>>(
        x1h, x1l, DD, Woth, Wotl, DD, y, DD, bo, nullptr, 1.0f, DD);

    // launch 7: final residual + LN
    add_ln<<<MROWS, 128>>>(x1, y, g1, b1, out, nullptr, nullptr, 1);
}

// round 9
// speedup vs baseline: 6.6625x; 1.0617x over previous
#include <cuda_runtime.h>
#include <cuda_bf16.h>
#include <cuda_fp16.h>
#include <cstdint>
#include <math.h>

#define BB 4
#define LQ 2048
#define LK 2048
#define DD 512
#define HH 8
#define DH 64
#define MROWS (BB * LQ)            // 8192
#define BHN  (BB * HH)             // 32
#define KVLD 1024                  // packed KV row stride (K cols 0-511, V cols 512-1023)

// ===================== scratch (static device globals) ======================
__device__ __half g_Qb [(size_t)MROWS * DD];
__device__ __half g_Kb [(size_t)MROWS * DD];
__device__ __half g_Qh [(size_t)MROWS * DD];
__device__ __half g_KVh[(size_t)MROWS * KVLD];
__device__ __half g_attn[(size_t)MROWS * DD];
__device__ float  g_x1 [(size_t)MROWS * DD];
__device__ __half g_x1h[(size_t)MROWS * DD];
__device__ float  g_y  [(size_t)MROWS * DD];
__device__ __half g_Wqt [(size_t)DD * DD];
__device__ __half g_Wkvt[(size_t)2 * DD * DD];   // rows 0-511: Wk^T, 512-1023: Wv^T
__device__ __half g_Woth[(size_t)DD * DD];
__device__ __half g_Wotl[(size_t)DD * DD];

// ===================== low-level helpers (sm_80+ only) ======================
__device__ __forceinline__ uint32_t smem_u32(const void* p) {
    uint32_t a;
    asm("{ .reg .u64 t; cvta.to.shared.u64 t, %1; cvt.u32.u64 %0, t; }"
        : "=r"(a) : "l"(p));
    return a;
}
__device__ __forceinline__ void cp_async16(uint32_t dst, const void* src) {
    asm volatile("cp.async.cg.shared.global [%0], [%1], 16;"
                 :: "r"(dst), "l"(src) : "memory");
}
#define CP_COMMIT() asm volatile("cp.async.commit_group;" ::: "memory")

__device__ __forceinline__ void ldm_x4(uint32_t* r, uint32_t addr) {
    asm volatile("ldmatrix.sync.aligned.m8n8.x4.shared.b16 {%0,%1,%2,%3}, [%4];"
                 : "=r"(r[0]), "=r"(r[1]), "=r"(r[2]), "=r"(r[3]) : "r"(addr));
}
__device__ __forceinline__ void ldm_x4_t(uint32_t* r, uint32_t addr) {
    asm volatile("ldmatrix.sync.aligned.m8n8.x4.trans.shared.b16 {%0,%1,%2,%3}, [%4];"
                 : "=r"(r[0]), "=r"(r[1]), "=r"(r[2]), "=r"(r[3]) : "r"(addr));
}
__device__ __forceinline__ void ldm_x2(uint32_t* r, uint32_t addr) {
    asm volatile("ldmatrix.sync.aligned.m8n8.x2.shared.b16 {%0,%1}, [%2];"
                 : "=r"(r[0]), "=r"(r[1]) : "r"(addr));
}
__device__ __forceinline__ void mma_f16(float* d, const uint32_t* a, const uint32_t* b) {
    asm volatile(
        "mma.sync.aligned.m16n8k16.row.col.f32.f16.f16.f32 "
        "{%0,%1,%2,%3}, {%4,%5,%6,%7}, {%8,%9}, {%0,%1,%2,%3};"
        : "+f"(d[0]), "+f"(d[1]), "+f"(d[2]), "+f"(d[3])
        : "r"(a[0]), "r"(a[1]), "r"(a[2]), "r"(a[3]), "r"(b[0]), "r"(b[1]));
}
__device__ __forceinline__ float fexp2(float x) {
    float y;
    asm("ex2.approx.f32 %0, %1;" : "=f"(y) : "f"(x));
    return y;
}
// pack (lo, hi) -> f16x2, then elementwise exp2. Result IS a P-fragment register.
__device__ __forceinline__ uint32_t pexp2(float lo, float hi) {
    uint32_t h, r;
    asm("cvt.rn.f16x2.f32 %0, %1, %2;" : "=r"(h) : "f"(hi), "f"(lo));
    asm("ex2.approx.f16x2 %0, %1;" : "=r"(r) : "r"(h));
    return r;
}

// ===================== generic warp-MMA GEMM (fp16) =========================
// D[128, BN-tile of N] = sum_K A[128,K] * B[N,K]^T  (fp16 in, fp32 accum)
// TERMS==2: B = Bhi + Blo (fp16 hi/lo split); computes A*Bhi + A*Blo.
// OUTT: 0 = fp32, 2 = fp16 output.
// NS==4: single-barrier-per-k-step schedule (stage (kt+2)%4 last read at
// compute(kt-2), finished before barrier of iteration kt-1 -> safe).
template<int BN, int TERMS, int OUTT, bool HAS_BIAS, int NS>
__global__ __launch_bounds__(256)
void mma_gemm(const __half* __restrict__ A, long long lda,
              const __half* __restrict__ Bhi, const __half* __restrict__ Blo,
              long long ldb,
              void* __restrict__ Cout, long long ldc,
              const float* __restrict__ bias, const float* __restrict__ bias2,
              float outScale, int Ksz)
{
    constexpr int LDS   = 40;                  // padded row (elements): 80B stride
    constexpr int A_ELE = 128 * LDS;
    constexpr int B_ELE = BN * LDS;
    constexpr int STAGE = A_ELE + TERMS * B_ELE;
    constexpr int WN    = BN / 4;
    constexpr int NT_   = WN / 8;

    extern __shared__ __align__(16) __half sm_[];
    const int tid = threadIdx.x, wid = tid >> 5, lane = tid & 31;
    const int warp_m = wid & 1, warp_n = wid >> 1;
    const int m0 = blockIdx.y * 128, n0b = blockIdx.x * BN;

    const __half* Ab  = A   + (long long)m0  * lda;
    const __half* Bb  = Bhi + (long long)n0b * ldb;
    const __half* Bbl = (TERMS == 2) ? (Blo + (long long)n0b * ldb) : nullptr;

    const uint32_t sbase = smem_u32(sm_);

    float acc[4][NT_][4];
#pragma unroll
    for (int i = 0; i < 4; i++)
#pragma unroll
        for (int j = 0; j < NT_; j++)
#pragma unroll
            for (int k = 0; k < 4; k++) acc[i][j][k] = 0.f;

    auto load_stage = [&](int kt, int s) {
        const int koff = kt * 32;
        const uint32_t stA = sbase + (uint32_t)(s * STAGE) * 2;
        const uint32_t stB = stA + (uint32_t)A_ELE * 2;
#pragma unroll
        for (int i = tid; i < 512; i += 256) {
            int r = i >> 2, c = i & 3;
            cp_async16(stA + (uint32_t)(r * LDS + c * 8) * 2,
                       Ab + (long long)r * lda + koff + c * 8);
        }
#pragma unroll
        for (int i = tid; i < BN * 4; i += 256) {
            int r = i >> 2, c = i & 3;
            cp_async16(stB + (uint32_t)(r * LDS + c * 8) * 2,
                       Bb + (long long)r * ldb + koff + c * 8);
        }
        if (TERMS == 2) {
#pragma unroll
            for (int i = tid; i < BN * 4; i += 256) {
                int r = i >> 2, c = i & 3;
                cp_async16(stB + (uint32_t)(B_ELE + r * LDS + c * 8) * 2,
                           Bbl + (long long)r * ldb + koff + c * 8);
            }
        }
        CP_COMMIT();
    };

    auto compute_stage = [&](int s) {
        const uint32_t aB = sbase + (uint32_t)(s * STAGE) * 2;
        const uint32_t bBase0 = aB + (uint32_t)A_ELE * 2;
#pragma unroll
        for (int t = 0; t < TERMS; t++) {
            const uint32_t bB = bBase0 + (uint32_t)(t * B_ELE) * 2;
#pragma unroll
            for (int ks = 0; ks < 2; ks++) {
                uint32_t af[4][4], bf[NT_][2];
#pragma unroll
                for (int mt = 0; mt < 4; mt++) {
                    uint32_t addr = aB + (uint32_t)(
                        (warp_m * 64 + mt * 16 + (lane & 15)) * LDS
                        + ks * 16 + ((lane >> 4) << 3)) * 2;
                    ldm_x4(af[mt], addr);
                }
#pragma unroll
                for (int nt = 0; nt < NT_; nt++) {
                    uint32_t addr = bB + (uint32_t)(
                        (warp_n * WN + nt * 8 + (lane & 7)) * LDS
                        + ks * 16 + (((lane >> 3) & 1) << 3)) * 2;
                    ldm_x2(bf[nt], addr);
                }
#pragma unroll
                for (int mt = 0; mt < 4; mt++)
#pragma unroll
                    for (int nt = 0; nt < NT_; nt++)
                        mma_f16(acc[mt][nt], af[mt], bf[nt]);
            }
        }
    };

    const int KT = Ksz >> 5;
    if (NS == 4) {
        load_stage(0, 0);
        if (KT > 1) load_stage(1, 1);
        for (int kt = 0; kt < KT; kt++) {
            if (kt + 2 < KT) {
                load_stage(kt + 2, (kt + 2) & 3);
                asm volatile("cp.async.wait_group 2;" ::: "memory");
            } else if (kt + 1 < KT) {
                asm volatile("cp.async.wait_group 1;" ::: "memory");
            } else {
                asm volatile("cp.async.wait_group 0;" ::: "memory");
            }
            __syncthreads();
            compute_stage(kt & 3);
        }
    } else {
        load_stage(0, 0);
        for (int kt = 0; kt < KT; kt++) {
            if (kt + 1 < KT) {
                load_stage(kt + 1, (kt + 1) & 1);
                asm volatile("cp.async.wait_group 1;" ::: "memory");
            } else {
                asm volatile("cp.async.wait_group 0;" ::: "memory");
            }
            __syncthreads();
            compute_stage(kt & 1);
            __syncthreads();
        }
    }

    // epilogue
#pragma unroll
    for (int mt = 0; mt < 4; mt++) {
        const int rb = m0 + warp_m * 64 + mt * 16 + (lane >> 2);
#pragma unroll
        for (int nt = 0; nt < NT_; nt++) {
            const int c0 = n0b + warp_n * WN + nt * 8 + (lane & 3) * 2;
            float bx = 0.f, by = 0.f;
            if (HAS_BIAS) {
                if (bias2 && c0 >= 512) { bx = bias2[c0 - 512]; by = bias2[c0 - 511]; }
                else                    { bx = bias[c0];        by = bias[c0 + 1];    }
            }
#pragma unroll
            for (int half = 0; half < 2; half++) {
                const int r = rb + half * 8;
                float x0 = (acc[mt][nt][half * 2 + 0] + bx) * outScale;
                float x1 = (acc[mt][nt][half * 2 + 1] + by) * outScale;
                if (OUTT == 2) {
                    __half* C = (__half*)Cout + (long long)r * ldc + c0;
                    *(__half2*)C = __floats2half2_rn(x0, x1);
                } else {
                    float* C = (float*)Cout + (long long)r * ldc + c0;
                    float2 v; v.x = x0; v.y = x1;
                    *(float2*)C = v;
                }
            }
        }
    }
}

// ===================== fused flash attention (fp16 mma.sync) ================
// Grid: (LQ/128, BHN). 256 threads = 8 warps; warp w owns rows 16w..16w+15.
// K/V in 128-key double-buffered stages, two 64-key compute subtiles each.
// Scores pre-scaled by log2e; P = ex2.approx.f16x2 of (s - m) pairs; masked
// keys get a -1e30 score bias (cvt -> -inf -> exp -> exact 0).
// l accumulated by an extra P @ ones MMA column, rescaled like O.
#define FBQ 128
#define FSK 128      // keys per load stage
#define FLDS 72      // padded row: 144 B stride -> ldmatrix conflict-free

__global__ __launch_bounds__(256, 2)
void flash_mma(const __half* __restrict__ Qh,
               const __half* __restrict__ KVh,
               const int* __restrict__ pad,
               __half* __restrict__ Out)
{
    extern __shared__ __align__(16) char fsm[];
    __half* Qs = (__half*)fsm;                  // 128*72
    __half* Ks = Qs + FBQ * FLDS;               // 2 * 128*72
    __half* Vs = Ks + 2 * FSK * FLDS;           // 2 * 128*72
    int*    Ms = (int*)(Vs + 2 * FSK * FLDS);   // 2 * 128

    const int tid = threadIdx.x, wid = tid >> 5, lane = tid & 31;
    const int q0 = blockIdx.x * FBQ;
    const int z = blockIdx.y, b = z >> 3, h = z & 7;
    const uint32_t sQ = smem_u32(Qs), sK = smem_u32(Ks);
    const uint32_t sV = smem_u32(Vs), sM = smem_u32(Ms);

    const __half* Qp = Qh + ((size_t)(b * LQ + q0)) * DD + h * DH;
    const __half* Kp = KVh + ((size_t)b * LK) * KVLD + h * DH;        // K cols
    const __half* Vp = KVh + ((size_t)b * LK) * KVLD + 512 + h * DH;  // V cols
    const int* pp = pad + b * LK;

    // Q tile -> smem
#pragma unroll
    for (int i = tid; i < 1024; i += 256) {
        int r = i >> 3, c = i & 7;
        cp_async16(sQ + (uint32_t)(r * FLDS + c * 8) * 2, Qp + (size_t)r * DD + c * 8);
    }
    CP_COMMIT();

    auto load_kv = [&](int st, int s) {
        const int k0 = st * FSK;
        const uint32_t kb = sK + (uint32_t)(s * FSK * FLDS) * 2;
        const uint32_t vb = sV + (uint32_t)(s * FSK * FLDS) * 2;
#pragma unroll
        for (int i = tid; i < 1024; i += 256) {
            int r = i >> 3, c = i & 7;
            cp_async16(kb + (uint32_t)(r * FLDS + c * 8) * 2,
                       Kp + (size_t)(k0 + r) * KVLD + c * 8);
            cp_async16(vb + (uint32_t)(r * FLDS + c * 8) * 2,
                       Vp + (size_t)(k0 + r) * KVLD + c * 8);
        }
        if (tid < 32)
            cp_async16(sM + (uint32_t)(s * FSK + tid * 4) * 4, pp + k0 + tid * 4);
        CP_COMMIT();
    };

    load_kv(0, 0);

    const uint32_t bones[2] = {0x3C003C00u, 0x3C003C00u};   // f16 ones fragment
    uint32_t qf[4][4];
    float o[8][4];
    float losum[4] = {0.f, 0.f, 0.f, 0.f};
#pragma unroll
    for (int i = 0; i < 8; i++)
#pragma unroll
        for (int j = 0; j < 4; j++) o[i][j] = 0.f;
    float m0 = -1e30f, m1 = -1e30f;

    const int NST = LK / FSK;   // 16
    for (int st = 0; st < NST; st++) {
        const int s = st & 1;
        if (st + 1 < NST) {
            load_kv(st + 1, s ^ 1);
            asm volatile("cp.async.wait_group 1;" ::: "memory");
        } else {
            asm volatile("cp.async.wait_group 0;" ::: "memory");
        }
        __syncthreads();
        if (st == 0) {
#pragma unroll
            for (int ks = 0; ks < 4; ks++) {
                uint32_t addr = sQ + (uint32_t)(
                    (wid * 16 + (lane & 15)) * FLDS + ks * 16 + ((lane >> 4) << 3)) * 2;
                ldm_x4(qf[ks], addr);
            }
        }

#pragma unroll
        for (int hk = 0; hk < 2; hk++) {
            const uint32_t kb = sK + (uint32_t)((s * FSK + hk * 64) * FLDS) * 2;
            const uint32_t vb = sV + (uint32_t)((s * FSK + hk * 64) * FLDS) * 2;
            const int* mskp = Ms + s * FSK + hk * 64;

            // ---- S = Q K^T (log2-domain scores) ----
            float sa[8][4];
#pragma unroll
            for (int i = 0; i < 8; i++)
#pragma unroll
                for (int j = 0; j < 4; j++) sa[i][j] = 0.f;
#pragma unroll
            for (int ks = 0; ks < 4; ks++) {
                uint32_t bk[8][2];
#pragma unroll
                for (int np = 0; np < 4; np++) {
                    uint32_t r4[4];
                    uint32_t addr = kb + (uint32_t)(
                        (np * 16 + (lane & 15)) * FLDS + ks * 16 + ((lane >> 4) << 3)) * 2;
                    ldm_x4(r4, addr);
                    bk[2 * np][0] = r4[0]; bk[2 * np][1] = r4[2];
                    bk[2 * np + 1][0] = r4[1]; bk[2 * np + 1][1] = r4[3];
                }
#pragma unroll
                for (int nt = 0; nt < 8; nt++) mma_f16(sa[nt], qf[ks], bk[nt]);
            }

            // ---- mask via score bias, then plain max ----
            const int cb = (lane & 3) * 2;
#pragma unroll
            for (int nt = 0; nt < 8; nt++) {
                const float b0 = mskp[nt * 8 + cb]     ? 0.f : -1e30f;
                const float b1 = mskp[nt * 8 + cb + 1] ? 0.f : -1e30f;
                sa[nt][0] += b0; sa[nt][1] += b1;
                sa[nt][2] += b0; sa[nt][3] += b1;
            }
            float mx0 = sa[0][0], mx1 = sa[0][2];
#pragma unroll
            for (int nt = 0; nt < 8; nt++) {
                mx0 = fmaxf(mx0, fmaxf(sa[nt][0], sa[nt][1]));
                mx1 = fmaxf(mx1, fmaxf(sa[nt][2], sa[nt][3]));
            }
            mx0 = fmaxf(mx0, __shfl_xor_sync(~0u, mx0, 1));
            mx0 = fmaxf(mx0, __shfl_xor_sync(~0u, mx0, 2));
            mx1 = fmaxf(mx1, __shfl_xor_sync(~0u, mx1, 1));
            mx1 = fmaxf(mx1, __shfl_xor_sync(~0u, mx1, 2));
            const float mn0 = fmaxf(m0, mx0), mn1 = fmaxf(m1, mx1);
            const float al0 = fexp2(m0 - mn0), al1 = fexp2(m1 - mn1);
            m0 = mn0; m1 = mn1;

            // ---- P fragments: packed f16x2 exp2 of (s - m) ----
            uint32_t pf[4][4];
#pragma unroll
            for (int ks = 0; ks < 4; ks++) {
                pf[ks][0] = pexp2(sa[2 * ks][0] - mn0,     sa[2 * ks][1] - mn0);
                pf[ks][1] = pexp2(sa[2 * ks][2] - mn1,     sa[2 * ks][3] - mn1);
                pf[ks][2] = pexp2(sa[2 * ks + 1][0] - mn0, sa[2 * ks + 1][1] - mn0);
                pf[ks][3] = pexp2(sa[2 * ks + 1][2] - mn1, sa[2 * ks + 1][3] - mn1);
            }

            // ---- rescale O and l-accumulator ----
#pragma unroll
            for (int nt = 0; nt < 8; nt++) {
                o[nt][0] *= al0; o[nt][1] *= al0;
                o[nt][2] *= al1; o[nt][3] *= al1;
            }
            losum[0] *= al0; losum[1] *= al0;
            losum[2] *= al1; losum[3] *= al1;

            // ---- O += P V; l += P @ ones ----
#pragma unroll
            for (int ks = 0; ks < 4; ks++) {
                mma_f16(losum, pf[ks], bones);
#pragma unroll
                for (int np = 0; np < 4; np++) {
                    uint32_t r4[4];
                    uint32_t addr = vb + (uint32_t)(
                        (ks * 16 + (lane & 15)) * FLDS + np * 16 + ((lane >> 4) << 3)) * 2;
                    ldm_x4_t(r4, addr);
                    mma_f16(o[2 * np],     pf[ks], r4);
                    mma_f16(o[2 * np + 1], pf[ks], r4 + 2);
                }
            }
        }
        __syncthreads();
    }

    // ---- write O (losum[0]/losum[2] hold the exact row sums) ----
    const float l0 = losum[0], l1 = losum[2];
    const float inv0 = (l0 > 0.f) ? 1.f / l0 : 0.f;
    const float inv1 = (l1 > 0.f) ? 1.f / l1 : 0.f;
    const int r0g = q0 + wid * 16 + (lane >> 2);
    __half* ob0 = Out + ((size_t)(b * LQ + r0g)) * DD + h * DH + (lane & 3) * 2;
    __half* ob1 = ob0 + (size_t)8 * DD;
#pragma unroll
    for (int nt = 0; nt < 8; nt++) {
        *(__half2*)(ob0 + nt * 8) = __floats2half2_rn(o[nt][0] * inv0, o[nt][1] * inv0);
        *(__half2*)(ob1 + nt * 8) = __floats2half2_rn(o[nt][2] * inv1, o[nt][3] * inv1);
    }
}

// ===================== small helper kernels =================================
// grid.y selects source: 0 -> (Q -> Qb), 1 -> (K -> Kb)
__global__ __launch_bounds__(256) void cvt_f16_dual(
    const float* __restrict__ Qs, const float* __restrict__ Ksrc,
    __half* __restrict__ Qd, __half* __restrict__ Kd)
{
    const float* x = blockIdx.y ? Ksrc : Qs;
    __half* y = blockIdx.y ? Kd : Qd;
    size_t i = ((size_t)blockIdx.x * 256 + threadIdx.x) * 8;
    float4 a = *(const float4*)(x + i), b = *(const float4*)(x + i + 4);
    __half2 r0 = __floats2half2_rn(a.x, a.y);
    __half2 r1 = __floats2half2_rn(a.z, a.w);
    __half2 r2 = __floats2half2_rn(b.x, b.y);
    __half2 r3 = __floats2half2_rn(b.z, b.w);
    uint4 o;
    o.x = *(uint32_t*)&r0; o.y = *(uint32_t*)&r1;
    o.z = *(uint32_t*)&r2; o.w = *(uint32_t*)&r3;
    *(uint4*)(y + i) = o;
}

// fused weight transposes: z=0 Wq->Wqt, z=1 Wk->Wkvt[0:512], z=2 Wv->Wkvt[512:],
// z=3 Wo->Woth+Wotl (fp16 hi/lo split)
__global__ void tw_fused(const float* __restrict__ Wq, const float* __restrict__ Wk,
                         const float* __restrict__ Wv, const float* __restrict__ Wo,
                         __half* __restrict__ Wqt, __half* __restrict__ Wkvt,
                         __half* __restrict__ Woth, __half* __restrict__ Wotl)
{
    __shared__ float t[32][33];
    const int zz = blockIdx.z;
    const float* W = (zz == 0) ? Wq : (zz == 1) ? Wk : (zz == 2) ? Wv : Wo;
    __half* Th = (zz == 0) ? Wqt : (zz == 1) ? Wkvt
               : (zz == 2) ? (Wkvt + (size_t)512 * DD) : Woth;
    __half* Tl = (zz == 3) ? Wotl : nullptr;

    const int x = blockIdx.x * 32, y = blockIdx.y * 32;
    const int tx = threadIdx.x, ty = threadIdx.y;
    for (int i = ty; i < 32; i += 8)
        t[i][tx] = W[(size_t)(y + i) * DD + x + tx];
    __syncthreads();
    for (int i = ty; i < 32; i += 8) {
        float v = t[tx][i];
        __half hb = __float2half_rn(v);
        Th[(size_t)(x + i) * DD + y + tx] = hb;
        if (Tl) Tl[(size_t)(x + i) * DD + y + tx] =
            __float2half_rn(v - __half2float(hb));
    }
}

// residual + layernorm. relu_mode=0: t = X + Y; 1: t = X + relu(Y).
// Y comes from Yh (fp16) if non-null, else Yf (fp32).
// Optionally emits fp16 copy of the result (for the Wo GEMM A operand).
__global__ __launch_bounds__(128) void add_ln(
    const float* __restrict__ X, const float* __restrict__ Yf,
    const __half* __restrict__ Yh,
    const float* __restrict__ g, const float* __restrict__ beta,
    float* __restrict__ out, __half* __restrict__ oh, int relu_mode)
{
    const int row = blockIdx.x;
    const int tid = threadIdx.x;
    const size_t base = (size_t)row * DD;
    const int c4 = tid * 4;

    float4 xa = *(const float4*)(X + base + c4);
    float ya[4];
    if (Yh) {
        uint2 raw = *(const uint2*)(Yh + base + c4);
        __half2 h0 = *(__half2*)&raw.x, h1 = *(__half2*)&raw.y;
        float2 f0 = __half22float2(h0), f1 = __half22float2(h1);
        ya[0] = f0.x; ya[1] = f0.y; ya[2] = f1.x; ya[3] = f1.y;
    } else {
        float4 yv = *(const float4*)(Yf + base + c4);
        ya[0] = yv.x; ya[1] = yv.y; ya[2] = yv.z; ya[3] = yv.w;
    }
    float xv[4] = {xa.x, xa.y, xa.z, xa.w};
    float v[4];
#pragma unroll
    for (int i = 0; i < 4; i++)
        v[i] = relu_mode ? (xv[i] + fmaxf(ya[i], 0.f)) : (xv[i] + ya[i]);
    float s = 0.f, s2 = 0.f;
#pragma unroll
    for (int i = 0; i < 4; i++) { s += v[i]; s2 = fmaf(v[i], v[i], s2); }
#pragma unroll
    for (int o = 16; o > 0; o >>= 1) {
        s  += __shfl_xor_sync(~0u, s, o);
        s2 += __shfl_xor_sync(~0u, s2, o);
    }
    __shared__ float sh[8];
    int w = tid >> 5;
    if ((tid & 31) == 0) { sh[w] = s; sh[4 + w] = s2; }
    __syncthreads();
    if (tid == 0) {
        float S1 = sh[0] + sh[1] + sh[2] + sh[3];
        float S2 = sh[4] + sh[5] + sh[6] + sh[7];
        float mean = S1 * (1.f / DD);
        float var  = S2 * (1.f / DD) - mean * mean;
        sh[0] = mean;
        sh[1] = rsqrtf(var + 1e-5f);
    }
    __syncthreads();
    const float mean = sh[0], rstd = sh[1];
    const float4 gg = *(const float4*)(g + c4);
    const float4 bb = *(const float4*)(beta + c4);
    float4 ov;
    ov.x = (v[0] - mean) * rstd * gg.x + bb.x;
    ov.y = (v[1] - mean) * rstd * gg.y + bb.y;
    ov.z = (v[2] - mean) * rstd * gg.z + bb.z;
    ov.w = (v[3] - mean) * rstd * gg.w + bb.w;
    *(float4*)(out + base + c4) = ov;
    if (oh) {
        __half2 h0 = __floats2half2_rn(ov.x, ov.y);
        __half2 h1 = __floats2half2_rn(ov.z, ov.w);
        uint2 ho = {*(uint32_t*)&h0, *(uint32_t*)&h1};
        *(uint2*)(oh + base + c4) = ho;
    }
}

// ===================== launch ===============================================
extern "C" void kernel_launch(void* const* d_in, const int* in_sizes, int n_in,
                              void* d_out, int out_size)
{
    const float* Q   = (const float*)d_in[0];
    const float* K   = (const float*)d_in[1];
    const int*   pad = (const int*)  d_in[2];
    const float* Wq  = (const float*)d_in[3];  const float* bq = (const float*)d_in[4];
    const float* Wk  = (const float*)d_in[5];  const float* bk = (const float*)d_in[6];
    const float* Wv  = (const float*)d_in[7];  const float* bv = (const float*)d_in[8];
    const float* Wo  = (const float*)d_in[9];  const float* bo = (const float*)d_in[10];
    const float* g0  = (const float*)d_in[11]; const float* b0 = (const float*)d_in[12];
    const float* g1  = (const float*)d_in[13]; const float* b1 = (const float*)d_in[14];
    float* out = (float*)d_out;

    __half *Qb, *Kb, *Qh, *KVh, *attn, *x1h, *Wqt, *Wkvt, *Woth, *Wotl;
    float *x1, *y;
    cudaGetSymbolAddress((void**)&Qb,   g_Qb);   cudaGetSymbolAddress((void**)&Kb,   g_Kb);
    cudaGetSymbolAddress((void**)&Qh,   g_Qh);   cudaGetSymbolAddress((void**)&KVh,  g_KVh);
    cudaGetSymbolAddress((void**)&attn, g_attn); cudaGetSymbolAddress((void**)&x1,   g_x1);
    cudaGetSymbolAddress((void**)&x1h,  g_x1h);
    cudaGetSymbolAddress((void**)&y,    g_y);
    cudaGetSymbolAddress((void**)&Wqt,  g_Wqt);  cudaGetSymbolAddress((void**)&Wkvt, g_Wkvt);
    cudaGetSymbolAddress((void**)&Woth, g_Woth); cudaGetSymbolAddress((void**)&Wotl, g_Wotl);

    const int smem_g1 = 4 * (128 + 128) * 40 * 2;       // 81920 (4-stage, 1 term)
    const int smem_g2 = 2 * (128 + 2 * 128) * 40 * 2;   // 61440 (2-stage, 2 terms)
    const int smem_fl = (FBQ * FLDS + 4 * FSK * FLDS) * 2 + 2 * FSK * 4;  // 93184
    cudaFuncSetAttribute((const void*)mma_gemm<128, 1, 2, true, 4>,
                         cudaFuncAttributeMaxDynamicSharedMemorySize, smem_g1);
    cudaFuncSetAttribute((const void*)mma_gemm<128, 2, 0, true, 2>,
                         cudaFuncAttributeMaxDynamicSharedMemorySize, smem_g2);
    cudaFuncSetAttribute((const void*)flash_mma,
                         cudaFuncAttributeMaxDynamicSharedMemorySize, smem_fl);

    // 1/sqrt(512) * log2(e): scores land in log2 domain for ex2-based softmax
    const float qscale = 0.04419417382415922f * 1.4426950408889634f;

    // launch 0: input conversions (Q and K in one launch, fp16)
    cvt_f16_dual<<<dim3((MROWS * DD) / (256 * 8), 2), 256>>>(Q, K, Qb, Kb);
    // launch 1: all weight transposes (fp16; Wo hi/lo)
    tw_fused<<<dim3(16, 16, 4), dim3(32, 8)>>>(Wq, Wk, Wv, Wo, Wqt, Wkvt, Woth, Wotl);

    // launch 2: Q projection (pre-scaled, fp16 out)
    dim3 pgq(DD / 128, MROWS / 128);
    mma_gemm<128, 1, 2, true, 4><<<pgq, 256, smem_g1>>>(
        Qb, DD, Wqt, nullptr, DD, Qh, DD, bq, nullptr, qscale, DD);
    // launch 3: fused K+V projection into packed KV (N = 1024, fp16 out)
    dim3 pgkv(KVLD / 128, MROWS / 128);
    mma_gemm<128, 1, 2, true, 4><<<pgkv, 256, smem_g1>>>(
        Kb, DD, Wkvt, nullptr, DD, KVh, KVLD, bk, bv, 1.0f, DD);

    // launch 4: fused attention (fp16 out)
    flash_mma<<<dim3(LQ / FBQ, BHN), 256, smem_fl>>>(Qh, KVh, pad, attn);

    // launch 5: residual + LN (attn read as fp16; emits x1 fp32 + fp16)
    add_ln<<<MROWS, 128>>>(Q, nullptr, attn, g0, b0, x1, x1h, 0);

    // launch 6: Wo GEMM, 2-term fp16 hi/lo split of Wo
    mma_gemm<128, 2, 0, true, 2><<<pgq, 256, smem_g2>>>(
        x1h, DD, Woth, Wotl, DD, y, DD, bo, nullptr, 1.0f, DD);

    // launch 7: final residual + LN
    add_ln<<<MROWS, 128>>>(x1, y, nullptr, g1, b1, out, nullptr, 1);
}